// round 2
// baseline (speedup 1.0000x reference)
#include <cuda_runtime.h>
#include <cuda_bf16.h>
#include <math.h>

#define S_LEN 4096
#define EMB   2048
#define NHEADS 16
#define NKVH   4
#define HDv    128

// ------------------- scratch (device globals; no allocations) -------------------
__device__ float g_q [S_LEN * EMB];          // Q projection  [s][h*128+d]
__device__ float g_k [S_LEN * NKVH * HDv];   // K projection  [s][kvh*128+d]
__device__ float g_v [S_LEN * NKVH * HDv];   // V projection  [s][kvh*128+d]
__device__ float g_qt[NHEADS * HDv * S_LEN]; // RoPE'd Q, d-major: [h][d][s]
__device__ float g_kt[NKVH  * HDv * S_LEN];  // RoPE'd K, d-major: [kvh][d][s]
__device__ float g_ao[S_LEN * EMB];          // attention out [s][h*128+d]

// ------------------- SGEMM: C[M,N] = A[M,K] @ B[K,N], row-major -------------------
// M%128==0, N%128==0, K%16==0. 256 threads, 128x128 tile, 8x8 per thread.
// Register-prefetch pipelining: next k-slice GMEM loads issued before compute.
__global__ __launch_bounds__(256) void sgemm_kernel(
    const float* __restrict__ A, const float* __restrict__ B,
    float* __restrict__ C, int M, int N, int K)
{
    __shared__ float As[16][128];
    __shared__ float Bs[16][128];
    const int tid = threadIdx.x;
    const int tx = tid & 15, ty = tid >> 4;
    const int row0 = blockIdx.y * 128;
    const int col0 = blockIdx.x * 128;

    // per-thread load coordinates (2 float4 for A, 2 float4 for B per k-step)
    const int l0 = tid * 2, l1 = tid * 2 + 1;
    const int ar0 = l0 >> 2, ac0 = (l0 & 3) << 2;
    const int ar1 = l1 >> 2, ac1 = (l1 & 3) << 2;
    const int br0 = l0 >> 5, bc0 = (l0 & 31) << 2;
    const int br1 = l1 >> 5, bc1 = (l1 & 31) << 2;

    const float* Ap0 = A + (size_t)(row0 + ar0) * K + ac0;
    const float* Ap1 = A + (size_t)(row0 + ar1) * K + ac1;
    const float* Bp0 = B + (size_t)br0 * N + col0 + bc0;
    const float* Bp1 = B + (size_t)br1 * N + col0 + bc1;

    float acc[8][8];
#pragma unroll
    for (int i = 0; i < 8; i++)
#pragma unroll
        for (int j = 0; j < 8; j++) acc[i][j] = 0.f;

    // prologue: fetch k-slice 0
    float4 ra0 = *(const float4*)Ap0;
    float4 ra1 = *(const float4*)Ap1;
    float4 rb0 = *(const float4*)Bp0;
    float4 rb1 = *(const float4*)Bp1;

    for (int k0 = 0; k0 < K; k0 += 16) {
        // store current slice to smem
        As[ac0 + 0][ar0] = ra0.x; As[ac0 + 1][ar0] = ra0.y;
        As[ac0 + 2][ar0] = ra0.z; As[ac0 + 3][ar0] = ra0.w;
        As[ac1 + 0][ar1] = ra1.x; As[ac1 + 1][ar1] = ra1.y;
        As[ac1 + 2][ar1] = ra1.z; As[ac1 + 3][ar1] = ra1.w;
        *(float4*)&Bs[br0][bc0] = rb0;
        *(float4*)&Bs[br1][bc1] = rb1;
        __syncthreads();

        // prefetch next slice (overlaps with FMA block below)
        if (k0 + 16 < K) {
            ra0 = *(const float4*)(Ap0 + k0 + 16);
            ra1 = *(const float4*)(Ap1 + k0 + 16);
            rb0 = *(const float4*)(Bp0 + (size_t)(k0 + 16) * N);
            rb1 = *(const float4*)(Bp1 + (size_t)(k0 + 16) * N);
        }

#pragma unroll
        for (int kk = 0; kk < 16; kk++) {
            float4 a0 = *(const float4*)&As[kk][ty * 8];
            float4 a1 = *(const float4*)&As[kk][ty * 8 + 4];
            float4 b0 = *(const float4*)&Bs[kk][tx * 8];
            float4 b1 = *(const float4*)&Bs[kk][tx * 8 + 4];
            float av[8] = {a0.x, a0.y, a0.z, a0.w, a1.x, a1.y, a1.z, a1.w};
            float bv[8] = {b0.x, b0.y, b0.z, b0.w, b1.x, b1.y, b1.z, b1.w};
#pragma unroll
            for (int i = 0; i < 8; i++)
#pragma unroll
                for (int j = 0; j < 8; j++)
                    acc[i][j] = fmaf(av[i], bv[j], acc[i][j]);
        }
        __syncthreads();
    }
#pragma unroll
    for (int i = 0; i < 8; i++) {
#pragma unroll
        for (int j = 0; j < 8; j += 4) {
            float4 v = make_float4(acc[i][j], acc[i][j+1], acc[i][j+2], acc[i][j+3]);
            *(float4*)&C[(size_t)(row0 + ty * 8 + i) * N + col0 + tx * 8 + j] = v;
        }
    }
}

// ------------------- RoPE + transpose to d-major layout -------------------
// Q also gets the 1/sqrt(HD) scale folded in.
__global__ void rope_q_kernel(const int* __restrict__ pos_ids) {
    int s = blockIdx.x, h = blockIdx.y, d = threadIdx.x;  // d in [0,64)
    double inv = pow(1000000.0, -(double)d / 64.0);
    double ang = (double)pos_ids[s] * inv;
    double sd, cd; sincos(ang, &sd, &cd);
    float c = (float)cd, sn = (float)sd;
    const float* src = g_q + (size_t)s * EMB + h * HDv;
    float x0 = src[d], x1 = src[d + 64];
    const float sc = 0.08838834764831845f;  // 1/sqrt(128)
    g_qt[(size_t)(h * HDv + d) * S_LEN + s]      = (x0 * c - x1 * sn) * sc;
    g_qt[(size_t)(h * HDv + d + 64) * S_LEN + s] = (x1 * c + x0 * sn) * sc;
}

__global__ void rope_k_kernel(const int* __restrict__ pos_ids) {
    int s = blockIdx.x, h = blockIdx.y, d = threadIdx.x;
    double inv = pow(1000000.0, -(double)d / 64.0);
    double ang = (double)pos_ids[s] * inv;
    double sd, cd; sincos(ang, &sd, &cd);
    float c = (float)cd, sn = (float)sd;
    const float* src = g_k + (size_t)s * (NKVH * HDv) + h * HDv;
    float x0 = src[d], x1 = src[d + 64];
    g_kt[(size_t)(h * HDv + d) * S_LEN + s]      = x0 * c - x1 * sn;
    g_kt[(size_t)(h * HDv + d + 64) * S_LEN + s] = x1 * c + x0 * sn;
}

// ------------------- Flash attention (causal, GQA) -------------------
// Grid: (64 qblocks, 16 heads), 256 threads. BM=BN=64, HD=128, fp32.
// Smem: QT[128][64] + KT[128][64] + VS[64][128] + PS[64][66]
#define FA_SMEM_FLOATS (128*64 + 128*64 + 64*128 + 64*66)

__global__ __launch_bounds__(256) void flash_kernel() {
    extern __shared__ float sm[];
    float* QT = sm;                 // [128][64]  d-major
    float* KT = QT + 128 * 64;      // [128][64]  d-major
    float* VS = KT + 128 * 64;      // [64][128]  n-major
    float* PS = VS + 64 * 128;      // [64][66]   probs (padded)

    const int h  = blockIdx.y;
    const int qb = (int)gridDim.x - 1 - (int)blockIdx.x;  // long CTAs first
    const int q0 = qb * 64;
    const int kvh = h >> 2;
    const int tid = threadIdx.x;
    const int tx = tid & 15, ty = tid >> 4;

    const float* qtg = g_qt + (size_t)h * HDv * S_LEN;
    const float* ktg = g_kt + (size_t)kvh * HDv * S_LEN;
    const float* vg  = g_v + kvh * HDv;

    // Load Q tile (coalesced float4; conflict-free smem writes, width 64)
#pragma unroll
    for (int it = 0; it < 8; it++) {
        int idx = tid + it * 256;
        int d = idx >> 4, m4 = (idx & 15) << 2;
        *(float4*)&QT[d * 64 + m4] = *(const float4*)&qtg[(size_t)d * S_LEN + q0 + m4];
    }

    float m_run[4], l_run[4], acc_o[4][8];
#pragma unroll
    for (int i = 0; i < 4; i++) {
        m_run[i] = -1e30f; l_run[i] = 0.f;
#pragma unroll
        for (int j = 0; j < 8; j++) acc_o[i][j] = 0.f;
    }
    __syncthreads();

    for (int kb = 0; kb <= qb; kb++) {
        const int k0 = kb * 64;
#pragma unroll
        for (int it = 0; it < 8; it++) {
            int idx = tid + it * 256;
            int d = idx >> 4, n4 = (idx & 15) << 2;
            *(float4*)&KT[d * 64 + n4] = *(const float4*)&ktg[(size_t)d * S_LEN + k0 + n4];
        }
#pragma unroll
        for (int it = 0; it < 8; it++) {
            int idx = tid + it * 256;
            int n = idx >> 5, d4 = (idx & 31) << 2;
            *(float4*)&VS[n * 128 + d4] =
                *(const float4*)&vg[(size_t)(k0 + n) * (NKVH * HDv) + d4];
        }
        __syncthreads();

        // S = Q K^T  (4x4 per thread; reads broadcast / conflict-free LDS.128)
        float s_acc[4][4];
#pragma unroll
        for (int i = 0; i < 4; i++)
#pragma unroll
            for (int j = 0; j < 4; j++) s_acc[i][j] = 0.f;
#pragma unroll 8
        for (int kk = 0; kk < 128; kk++) {
            float4 a = *(const float4*)&QT[kk * 64 + ty * 4];
            float4 b = *(const float4*)&KT[kk * 64 + tx * 4];
            float av[4] = {a.x, a.y, a.z, a.w};
            float bv[4] = {b.x, b.y, b.z, b.w};
#pragma unroll
            for (int i = 0; i < 4; i++)
#pragma unroll
                for (int j = 0; j < 4; j++)
                    s_acc[i][j] = fmaf(av[i], bv[j], s_acc[i][j]);
        }

        if (kb == qb) {  // causal mask on diagonal block (q0 == k0)
#pragma unroll
            for (int i = 0; i < 4; i++)
#pragma unroll
                for (int j = 0; j < 4; j++)
                    if (tx * 4 + j > ty * 4 + i) s_acc[i][j] = -1e30f;
        }

        // online softmax; each 16-lane row-group keeps identical m/l in regs
#pragma unroll
        for (int i = 0; i < 4; i++) {
            float mv = fmaxf(fmaxf(s_acc[i][0], s_acc[i][1]),
                             fmaxf(s_acc[i][2], s_acc[i][3]));
#pragma unroll
            for (int o = 1; o < 16; o <<= 1)
                mv = fmaxf(mv, __shfl_xor_sync(0xffffffffu, mv, o));
            float m_new = fmaxf(m_run[i], mv);
            float fs = __expf(m_run[i] - m_new);
            float sum = 0.f;
#pragma unroll
            for (int j = 0; j < 4; j++) {
                float p = __expf(s_acc[i][j] - m_new);
                s_acc[i][j] = p; sum += p;
            }
#pragma unroll
            for (int o = 1; o < 16; o <<= 1)
                sum += __shfl_xor_sync(0xffffffffu, sum, o);
            m_run[i] = m_new;
            l_run[i] = l_run[i] * fs + sum;
#pragma unroll
            for (int j = 0; j < 8; j++) acc_o[i][j] *= fs;
#pragma unroll
            for (int j = 0; j < 4; j++)
                PS[(ty * 4 + i) * 66 + tx * 4 + j] = s_acc[i][j];
        }
        __syncthreads();

        // O += P @ V  (P scalar-broadcast, V via LDS.128)
#pragma unroll 4
        for (int kk = 0; kk < 64; kk++) {
            float4 b0 = *(const float4*)&VS[kk * 128 + tx * 8];
            float4 b1 = *(const float4*)&VS[kk * 128 + tx * 8 + 4];
#pragma unroll
            for (int i = 0; i < 4; i++) {
                float p = PS[(ty * 4 + i) * 66 + kk];
                acc_o[i][0] = fmaf(p, b0.x, acc_o[i][0]);
                acc_o[i][1] = fmaf(p, b0.y, acc_o[i][1]);
                acc_o[i][2] = fmaf(p, b0.z, acc_o[i][2]);
                acc_o[i][3] = fmaf(p, b0.w, acc_o[i][3]);
                acc_o[i][4] = fmaf(p, b1.x, acc_o[i][4]);
                acc_o[i][5] = fmaf(p, b1.y, acc_o[i][5]);
                acc_o[i][6] = fmaf(p, b1.z, acc_o[i][6]);
                acc_o[i][7] = fmaf(p, b1.w, acc_o[i][7]);
            }
        }
        __syncthreads();
    }

    // epilogue: normalize and write [s][h*128+d]
#pragma unroll
    for (int i = 0; i < 4; i++) {
        int r = q0 + ty * 4 + i;
        float inv = 1.f / l_run[i];
        float4 o0 = make_float4(acc_o[i][0]*inv, acc_o[i][1]*inv, acc_o[i][2]*inv, acc_o[i][3]*inv);
        float4 o1 = make_float4(acc_o[i][4]*inv, acc_o[i][5]*inv, acc_o[i][6]*inv, acc_o[i][7]*inv);
        float* dst = g_ao + (size_t)r * EMB + h * HDv + tx * 8;
        *(float4*)dst = o0;
        *(float4*)(dst + 4) = o1;
    }
}

// ------------------- launch -------------------
extern "C" void kernel_launch(void* const* d_in, const int* in_sizes, int n_in,
                              void* d_out, int out_size)
{
    const float* hs = (const float*)d_in[0];
    const float* Wq = (const float*)d_in[1];
    const float* Wk = (const float*)d_in[2];
    const float* Wv = (const float*)d_in[3];
    const float* Wo = (const float*)d_in[4];
    // d_in[5] = attention_mask (pure causal; applied analytically)
    const int*   pos = (const int*)d_in[6];
    float* out = (float*)d_out;

    float *p_q, *p_k, *p_v, *p_ao;
    cudaGetSymbolAddress((void**)&p_q,  g_q);
    cudaGetSymbolAddress((void**)&p_k,  g_k);
    cudaGetSymbolAddress((void**)&p_v,  g_v);
    cudaGetSymbolAddress((void**)&p_ao, g_ao);

    cudaFuncSetAttribute(flash_kernel,
                         cudaFuncAttributeMaxDynamicSharedMemorySize,
                         FA_SMEM_FLOATS * sizeof(float));

    // 1) projections
    sgemm_kernel<<<dim3(EMB / 128, S_LEN / 128), 256>>>(hs, Wq, p_q, S_LEN, EMB, EMB);
    sgemm_kernel<<<dim3((NKVH*HDv) / 128, S_LEN / 128), 256>>>(hs, Wk, p_k, S_LEN, NKVH*HDv, EMB);
    sgemm_kernel<<<dim3((NKVH*HDv) / 128, S_LEN / 128), 256>>>(hs, Wv, p_v, S_LEN, NKVH*HDv, EMB);

    // 2) RoPE + transpose to d-major
    rope_q_kernel<<<dim3(S_LEN, NHEADS), 64>>>(pos);
    rope_k_kernel<<<dim3(S_LEN, NKVH), 64>>>(pos);

    // 3) causal flash attention
    flash_kernel<<<dim3(S_LEN / 64, NHEADS), 256, FA_SMEM_FLOATS * sizeof(float)>>>();

    // 4) output projection
    sgemm_kernel<<<dim3(EMB / 128, S_LEN / 128), 256>>>(p_ao, Wo, out, S_LEN, EMB, EMB);
}

// round 3
// speedup vs baseline: 1.2246x; 1.2246x over previous
#include <cuda_runtime.h>
#include <cuda_bf16.h>
#include <math.h>

#define S_LEN 4096
#define EMB   2048
#define NHEADS 16
#define NKVH   4
#define HDv    128

// ------------------- scratch (device globals; no allocations) -------------------
__device__ float g_q [S_LEN * EMB];          // Q projection  [s][h*128+d]
__device__ float g_k [S_LEN * NKVH * HDv];   // K projection  [s][kvh*128+d]
__device__ float g_v [S_LEN * NKVH * HDv];   // V projection  [s][kvh*128+d]
__device__ float g_qt[NHEADS * HDv * S_LEN]; // RoPE'd Q, d-major: [h][d][s]
__device__ float g_kt[NKVH  * HDv * S_LEN];  // RoPE'd K, d-major: [kvh][d][s]
__device__ float g_ao[S_LEN * EMB];          // attention out [s][h*128+d]
__device__ float g_cos[S_LEN * 64];          // RoPE cos table [s][d]
__device__ float g_sin[S_LEN * 64];          // RoPE sin table [s][d]

// ------------------- SGEMM: C[M,N] = A[M,K] @ B[K,N], row-major -------------------
// M%128==0, N%128==0, K%16==0. 256 threads, 128x128 tile, 8x8 per thread.
// Register-prefetch pipelining: next k-slice GMEM loads issued before compute.
__global__ __launch_bounds__(256) void sgemm_kernel(
    const float* __restrict__ A, const float* __restrict__ B,
    float* __restrict__ C, int M, int N, int K)
{
    __shared__ float As[16][128];
    __shared__ float Bs[16][128];
    const int tid = threadIdx.x;
    const int tx = tid & 15, ty = tid >> 4;
    const int row0 = blockIdx.y * 128;
    const int col0 = blockIdx.x * 128;

    const int l0 = tid * 2, l1 = tid * 2 + 1;
    const int ar0 = l0 >> 2, ac0 = (l0 & 3) << 2;
    const int ar1 = l1 >> 2, ac1 = (l1 & 3) << 2;
    const int br0 = l0 >> 5, bc0 = (l0 & 31) << 2;
    const int br1 = l1 >> 5, bc1 = (l1 & 31) << 2;

    const float* Ap0 = A + (size_t)(row0 + ar0) * K + ac0;
    const float* Ap1 = A + (size_t)(row0 + ar1) * K + ac1;
    const float* Bp0 = B + (size_t)br0 * N + col0 + bc0;
    const float* Bp1 = B + (size_t)br1 * N + col0 + bc1;

    float acc[8][8];
#pragma unroll
    for (int i = 0; i < 8; i++)
#pragma unroll
        for (int j = 0; j < 8; j++) acc[i][j] = 0.f;

    float4 ra0 = *(const float4*)Ap0;
    float4 ra1 = *(const float4*)Ap1;
    float4 rb0 = *(const float4*)Bp0;
    float4 rb1 = *(const float4*)Bp1;

    for (int k0 = 0; k0 < K; k0 += 16) {
        As[ac0 + 0][ar0] = ra0.x; As[ac0 + 1][ar0] = ra0.y;
        As[ac0 + 2][ar0] = ra0.z; As[ac0 + 3][ar0] = ra0.w;
        As[ac1 + 0][ar1] = ra1.x; As[ac1 + 1][ar1] = ra1.y;
        As[ac1 + 2][ar1] = ra1.z; As[ac1 + 3][ar1] = ra1.w;
        *(float4*)&Bs[br0][bc0] = rb0;
        *(float4*)&Bs[br1][bc1] = rb1;
        __syncthreads();

        if (k0 + 16 < K) {
            ra0 = *(const float4*)(Ap0 + k0 + 16);
            ra1 = *(const float4*)(Ap1 + k0 + 16);
            rb0 = *(const float4*)(Bp0 + (size_t)(k0 + 16) * N);
            rb1 = *(const float4*)(Bp1 + (size_t)(k0 + 16) * N);
        }

#pragma unroll
        for (int kk = 0; kk < 16; kk++) {
            float4 a0 = *(const float4*)&As[kk][ty * 8];
            float4 a1 = *(const float4*)&As[kk][ty * 8 + 4];
            float4 b0 = *(const float4*)&Bs[kk][tx * 8];
            float4 b1 = *(const float4*)&Bs[kk][tx * 8 + 4];
            float av[8] = {a0.x, a0.y, a0.z, a0.w, a1.x, a1.y, a1.z, a1.w};
            float bv[8] = {b0.x, b0.y, b0.z, b0.w, b1.x, b1.y, b1.z, b1.w};
#pragma unroll
            for (int i = 0; i < 8; i++)
#pragma unroll
                for (int j = 0; j < 8; j++)
                    acc[i][j] = fmaf(av[i], bv[j], acc[i][j]);
        }
        __syncthreads();
    }
#pragma unroll
    for (int i = 0; i < 8; i++) {
#pragma unroll
        for (int j = 0; j < 8; j += 4) {
            float4 v = make_float4(acc[i][j], acc[i][j+1], acc[i][j+2], acc[i][j+3]);
            *(float4*)&C[(size_t)(row0 + ty * 8 + i) * N + col0 + tx * 8 + j] = v;
        }
    }
}

// ------------------- RoPE table: one fp64 sincos per (s, d<64), computed ONCE ------
__global__ void rope_table_kernel(const int* __restrict__ pos_ids) {
    int s = blockIdx.x, d = threadIdx.x;  // d in [0,64)
    double inv = pow(1000000.0, -(double)d / 64.0);
    double ang = (double)pos_ids[s] * inv;
    double sd, cd; sincos(ang, &sd, &cd);
    g_cos[s * 64 + d] = (float)cd;
    g_sin[s * 64 + d] = (float)sd;
}

// ------------------- RoPE apply + transpose to d-major (pure memory op) -----------
// Block handles 32 s x 128 d for one head. All phases conflict-free (pitch 129).
__global__ __launch_bounds__(256) void rope_t_kernel(
    const float* __restrict__ src, float* __restrict__ dst,
    int src_stride, float sc)
{
    __shared__ float T[32 * 129];
    const int s0 = blockIdx.x * 32;
    const int h = blockIdx.y;
    const int tid = threadIdx.x;

    // phase 1: coalesced load (d fastest)
#pragma unroll
    for (int i = 0; i < 16; i++) {
        int idx = tid + i * 256;
        int sl = idx >> 7, d = idx & 127;
        T[sl * 129 + d] = src[(size_t)(s0 + sl) * src_stride + h * HDv + d];
    }
    __syncthreads();

    // phase 2: rotate pairs (d, d+64) in place; table reads coalesced
#pragma unroll
    for (int i = 0; i < 8; i++) {
        int idx = tid + i * 256;
        int sl = idx >> 6, d = idx & 63;
        float c  = g_cos[(s0 + sl) * 64 + d];
        float sn = g_sin[(s0 + sl) * 64 + d];
        float x0 = T[sl * 129 + d], x1 = T[sl * 129 + d + 64];
        T[sl * 129 + d]      = (x0 * c - x1 * sn) * sc;
        T[sl * 129 + d + 64] = (x1 * c + x0 * sn) * sc;
    }
    __syncthreads();

    // phase 3: coalesced transposed store (s fastest); smem stride 129 conflict-free
#pragma unroll
    for (int i = 0; i < 16; i++) {
        int idx = tid + i * 256;
        int d = idx >> 5, sl = idx & 31;
        dst[(size_t)(h * HDv + d) * S_LEN + s0 + sl] = T[sl * 129 + d];
    }
}

// ------------------- Flash attention (causal, GQA) -------------------
// Grid: (64 qblocks, 16 heads), 256 threads. BM=BN=64, HD=128, fp32.
#define FA_SMEM_FLOATS (128*64 + 128*64 + 64*128 + 64*66)

__global__ __launch_bounds__(256) void flash_kernel() {
    extern __shared__ float sm[];
    float* QT = sm;                 // [128][64]  d-major
    float* KT = QT + 128 * 64;      // [128][64]  d-major
    float* VS = KT + 128 * 64;      // [64][128]  n-major
    float* PS = VS + 64 * 128;      // [64][66]   probs (padded)

    const int h  = blockIdx.y;
    const int qb = (int)gridDim.x - 1 - (int)blockIdx.x;  // long CTAs first
    const int q0 = qb * 64;
    const int kvh = h >> 2;
    const int tid = threadIdx.x;
    const int tx = tid & 15, ty = tid >> 4;

    const float* qtg = g_qt + (size_t)h * HDv * S_LEN;
    const float* ktg = g_kt + (size_t)kvh * HDv * S_LEN;
    const float* vg  = g_v + kvh * HDv;

#pragma unroll
    for (int it = 0; it < 8; it++) {
        int idx = tid + it * 256;
        int d = idx >> 4, m4 = (idx & 15) << 2;
        *(float4*)&QT[d * 64 + m4] = *(const float4*)&qtg[(size_t)d * S_LEN + q0 + m4];
    }

    float m_run[4], l_run[4], acc_o[4][8];
#pragma unroll
    for (int i = 0; i < 4; i++) {
        m_run[i] = -1e30f; l_run[i] = 0.f;
#pragma unroll
        for (int j = 0; j < 8; j++) acc_o[i][j] = 0.f;
    }
    __syncthreads();

    for (int kb = 0; kb <= qb; kb++) {
        const int k0 = kb * 64;
#pragma unroll
        for (int it = 0; it < 8; it++) {
            int idx = tid + it * 256;
            int d = idx >> 4, n4 = (idx & 15) << 2;
            *(float4*)&KT[d * 64 + n4] = *(const float4*)&ktg[(size_t)d * S_LEN + k0 + n4];
        }
#pragma unroll
        for (int it = 0; it < 8; it++) {
            int idx = tid + it * 256;
            int n = idx >> 5, d4 = (idx & 31) << 2;
            *(float4*)&VS[n * 128 + d4] =
                *(const float4*)&vg[(size_t)(k0 + n) * (NKVH * HDv) + d4];
        }
        __syncthreads();

        float s_acc[4][4];
#pragma unroll
        for (int i = 0; i < 4; i++)
#pragma unroll
            for (int j = 0; j < 4; j++) s_acc[i][j] = 0.f;
#pragma unroll 8
        for (int kk = 0; kk < 128; kk++) {
            float4 a = *(const float4*)&QT[kk * 64 + ty * 4];
            float4 b = *(const float4*)&KT[kk * 64 + tx * 4];
            float av[4] = {a.x, a.y, a.z, a.w};
            float bv[4] = {b.x, b.y, b.z, b.w};
#pragma unroll
            for (int i = 0; i < 4; i++)
#pragma unroll
                for (int j = 0; j < 4; j++)
                    s_acc[i][j] = fmaf(av[i], bv[j], s_acc[i][j]);
        }

        if (kb == qb) {
#pragma unroll
            for (int i = 0; i < 4; i++)
#pragma unroll
                for (int j = 0; j < 4; j++)
                    if (tx * 4 + j > ty * 4 + i) s_acc[i][j] = -1e30f;
        }

#pragma unroll
        for (int i = 0; i < 4; i++) {
            float mv = fmaxf(fmaxf(s_acc[i][0], s_acc[i][1]),
                             fmaxf(s_acc[i][2], s_acc[i][3]));
#pragma unroll
            for (int o = 1; o < 16; o <<= 1)
                mv = fmaxf(mv, __shfl_xor_sync(0xffffffffu, mv, o));
            float m_new = fmaxf(m_run[i], mv);
            float fs = __expf(m_run[i] - m_new);
            float sum = 0.f;
#pragma unroll
            for (int j = 0; j < 4; j++) {
                float p = __expf(s_acc[i][j] - m_new);
                s_acc[i][j] = p; sum += p;
            }
#pragma unroll
            for (int o = 1; o < 16; o <<= 1)
                sum += __shfl_xor_sync(0xffffffffu, sum, o);
            m_run[i] = m_new;
            l_run[i] = l_run[i] * fs + sum;
#pragma unroll
            for (int j = 0; j < 8; j++) acc_o[i][j] *= fs;
#pragma unroll
            for (int j = 0; j < 4; j++)
                PS[(ty * 4 + i) * 66 + tx * 4 + j] = s_acc[i][j];
        }
        __syncthreads();

#pragma unroll 4
        for (int kk = 0; kk < 64; kk++) {
            float4 b0 = *(const float4*)&VS[kk * 128 + tx * 8];
            float4 b1 = *(const float4*)&VS[kk * 128 + tx * 8 + 4];
#pragma unroll
            for (int i = 0; i < 4; i++) {
                float p = PS[(ty * 4 + i) * 66 + kk];
                acc_o[i][0] = fmaf(p, b0.x, acc_o[i][0]);
                acc_o[i][1] = fmaf(p, b0.y, acc_o[i][1]);
                acc_o[i][2] = fmaf(p, b0.z, acc_o[i][2]);
                acc_o[i][3] = fmaf(p, b0.w, acc_o[i][3]);
                acc_o[i][4] = fmaf(p, b1.x, acc_o[i][4]);
                acc_o[i][5] = fmaf(p, b1.y, acc_o[i][5]);
                acc_o[i][6] = fmaf(p, b1.z, acc_o[i][6]);
                acc_o[i][7] = fmaf(p, b1.w, acc_o[i][7]);
            }
        }
        __syncthreads();
    }

#pragma unroll
    for (int i = 0; i < 4; i++) {
        int r = q0 + ty * 4 + i;
        float inv = 1.f / l_run[i];
        float4 o0 = make_float4(acc_o[i][0]*inv, acc_o[i][1]*inv, acc_o[i][2]*inv, acc_o[i][3]*inv);
        float4 o1 = make_float4(acc_o[i][4]*inv, acc_o[i][5]*inv, acc_o[i][6]*inv, acc_o[i][7]*inv);
        float* dst = g_ao + (size_t)r * EMB + h * HDv + tx * 8;
        *(float4*)dst = o0;
        *(float4*)(dst + 4) = o1;
    }
}

// ------------------- launch -------------------
extern "C" void kernel_launch(void* const* d_in, const int* in_sizes, int n_in,
                              void* d_out, int out_size)
{
    const float* hs = (const float*)d_in[0];
    const float* Wq = (const float*)d_in[1];
    const float* Wk = (const float*)d_in[2];
    const float* Wv = (const float*)d_in[3];
    const float* Wo = (const float*)d_in[4];
    // d_in[5] = attention_mask (pure causal; applied analytically)
    const int*   pos = (const int*)d_in[6];
    float* out = (float*)d_out;

    float *p_q, *p_k, *p_v, *p_ao, *p_qt, *p_kt;
    cudaGetSymbolAddress((void**)&p_q,  g_q);
    cudaGetSymbolAddress((void**)&p_k,  g_k);
    cudaGetSymbolAddress((void**)&p_v,  g_v);
    cudaGetSymbolAddress((void**)&p_ao, g_ao);
    cudaGetSymbolAddress((void**)&p_qt, g_qt);
    cudaGetSymbolAddress((void**)&p_kt, g_kt);

    cudaFuncSetAttribute(flash_kernel,
                         cudaFuncAttributeMaxDynamicSharedMemorySize,
                         FA_SMEM_FLOATS * sizeof(float));

    // 1) projections
    sgemm_kernel<<<dim3(EMB / 128, S_LEN / 128), 256>>>(hs, Wq, p_q, S_LEN, EMB, EMB);
    sgemm_kernel<<<dim3((NKVH*HDv) / 128, S_LEN / 128), 256>>>(hs, Wk, p_k, S_LEN, NKVH*HDv, EMB);
    sgemm_kernel<<<dim3((NKVH*HDv) / 128, S_LEN / 128), 256>>>(hs, Wv, p_v, S_LEN, NKVH*HDv, EMB);

    // 2) RoPE: table once, then memory-only apply+transpose
    rope_table_kernel<<<S_LEN, 64>>>(pos);
    rope_t_kernel<<<dim3(S_LEN / 32, NHEADS), 256>>>(p_q, p_qt, EMB, 0.08838834764831845f);
    rope_t_kernel<<<dim3(S_LEN / 32, NKVH),  256>>>(p_k, p_kt, NKVH * HDv, 1.0f);

    // 3) causal flash attention
    flash_kernel<<<dim3(S_LEN / 64, NHEADS), 256, FA_SMEM_FLOATS * sizeof(float)>>>();

    // 4) output projection
    sgemm_kernel<<<dim3(EMB / 128, S_LEN / 128), 256>>>(p_ao, Wo, out, S_LEN, EMB, EMB);
}

// round 7
// speedup vs baseline: 1.7593x; 1.4367x over previous
#include <cuda_runtime.h>
#include <cuda_bf16.h>
#include <math.h>
#include <stdint.h>

#define S_LEN 4096
#define EMB   2048
#define NHEADS 16
#define NKVH   4
#define HDv    128
#define KVD    (NKVH * HDv)   // 512

// ------------------- scratch (device globals; no allocations) -------------------
__device__ float g_q [S_LEN * EMB];
__device__ float g_k [S_LEN * KVD];
__device__ float g_v [S_LEN * KVD];
__device__ float g_qt[NHEADS * HDv * S_LEN];
__device__ float g_kt[NKVH  * HDv * S_LEN];
__device__ float g_ao[S_LEN * EMB];
__device__ float g_cos[S_LEN * 64];
__device__ float g_sin[S_LEN * 64];
// split-bf16 operands
__device__ __nv_bfloat16 g_ah [S_LEN * EMB], g_al [S_LEN * EMB];   // hidden_states hi/lo
__device__ __nv_bfloat16 g_aoh[S_LEN * EMB], g_aol[S_LEN * EMB];   // attn-out hi/lo
__device__ __nv_bfloat16 g_wqh[EMB * EMB], g_wql[EMB * EMB];       // Wq^T [N,K]
__device__ __nv_bfloat16 g_wkh[KVD * EMB], g_wkl[KVD * EMB];       // Wk^T
__device__ __nv_bfloat16 g_wvh[KVD * EMB], g_wvl[KVD * EMB];       // Wv^T
__device__ __nv_bfloat16 g_woh[EMB * EMB], g_wol[EMB * EMB];       // Wo^T

// ------------------- helpers -------------------
__device__ __forceinline__ uint32_t smem_u32(const void* p) {
    uint32_t a;
    asm("{ .reg .u64 t; cvta.to.shared.u64 t, %1; cvt.u32.u64 %0, t; }" : "=r"(a) : "l"(p));
    return a;
}
#define SMEM_SWZ(off) ((off) ^ (((off) >> 3) & 0x70))

#define LDSM4(r, a) \
    asm volatile("ldmatrix.sync.aligned.m8n8.x4.shared.b16 {%0,%1,%2,%3}, [%4];" \
        : "=r"((r)[0]), "=r"((r)[1]), "=r"((r)[2]), "=r"((r)[3]) : "r"(a))

#define MMA16816(d, a, b0v, b1v) \
    asm volatile("mma.sync.aligned.m16n8k16.row.col.f32.bf16.bf16.f32 " \
        "{%0,%1,%2,%3}, {%4,%5,%6,%7}, {%8,%9}, {%0,%1,%2,%3};" \
        : "+f"((d)[0]), "+f"((d)[1]), "+f"((d)[2]), "+f"((d)[3]) \
        : "r"((a)[0]), "r"((a)[1]), "r"((a)[2]), "r"((a)[3]), "r"(b0v), "r"(b1v))

#define CP_ASYNC16(s, g) \
    asm volatile("cp.async.cg.shared.global [%0], [%1], 16;" :: "r"(s), "l"(g))
#define CP_COMMIT() asm volatile("cp.async.commit_group;" ::: "memory")
#define CP_WAIT1()  asm volatile("cp.async.wait_group 1;" ::: "memory")
#define CP_WAIT0()  asm volatile("cp.async.wait_group 0;" ::: "memory")

// ------------------- split conversion: fp32 -> (hi, lo) bf16 -------------------
__global__ __launch_bounds__(256) void conv_split_kernel(
    const float* __restrict__ src, __nv_bfloat16* __restrict__ hi,
    __nv_bfloat16* __restrict__ lo, int n4)
{
    int i = blockIdx.x * 256 + threadIdx.x;
    if (i >= n4) return;
    float4 v = ((const float4*)src)[i];
    __nv_bfloat16 h0 = __float2bfloat16(v.x), h1 = __float2bfloat16(v.y);
    __nv_bfloat16 h2 = __float2bfloat16(v.z), h3 = __float2bfloat16(v.w);
    __nv_bfloat16 l0 = __float2bfloat16(v.x - __bfloat162float(h0));
    __nv_bfloat16 l1 = __float2bfloat16(v.y - __bfloat162float(h1));
    __nv_bfloat16 l2 = __float2bfloat16(v.z - __bfloat162float(h2));
    __nv_bfloat16 l3 = __float2bfloat16(v.w - __bfloat162float(h3));
    ((__nv_bfloat162*)hi)[i * 2]     = __nv_bfloat162(h0, h1);
    ((__nv_bfloat162*)hi)[i * 2 + 1] = __nv_bfloat162(h2, h3);
    ((__nv_bfloat162*)lo)[i * 2]     = __nv_bfloat162(l0, l1);
    ((__nv_bfloat162*)lo)[i * 2 + 1] = __nv_bfloat162(l2, l3);
}

// transpose + split: src [R,C] fp32 -> hi/lo [C,R] bf16
__global__ __launch_bounds__(256) void conv_split_t_kernel(
    const float* __restrict__ src, __nv_bfloat16* __restrict__ hi,
    __nv_bfloat16* __restrict__ lo, int R, int C)
{
    __shared__ float T[32][33];
    const int x = threadIdx.x, y = threadIdx.y;     // block (32, 8)
    const int c0 = blockIdx.x * 32, r0 = blockIdx.y * 32;
#pragma unroll
    for (int i = 0; i < 4; i++)
        T[y + 8 * i][x] = src[(size_t)(r0 + y + 8 * i) * C + c0 + x];
    __syncthreads();
#pragma unroll
    for (int i = 0; i < 4; i++) {
        int r = y + 8 * i;
        float v = T[x][r];
        __nv_bfloat16 h = __float2bfloat16(v);
        __nv_bfloat16 l = __float2bfloat16(v - __bfloat162float(h));
        size_t o = (size_t)(c0 + r) * R + r0 + x;
        hi[o] = h; lo[o] = l;
    }
}

// ------------------- mma.sync split-bf16 GEMM -------------------
// C[M,N] = A[M,K] @ Bt[N,K]^T  via Ah*Bh + Ah*Bl + Al*Bh (fp32 accum).
// CTA tile 128x128, K-chunks of 64, 2-stage cp.async pipeline, 8 warps (2x4),
// warp tile 64x32 (4 m-frags x 4 n-frags of m16n8k16).
// smem: 2 buffers x 64KB: [Ah 16K][Al 16K][Bh 16K][Bl 16K], 128B rows, swizzled.
#define TG_SMEM (2 * 65536)

__global__ __launch_bounds__(256, 1)
void tgemm_kernel(const __nv_bfloat16* __restrict__ Ah, const __nv_bfloat16* __restrict__ Al,
                  const __nv_bfloat16* __restrict__ Bh, const __nv_bfloat16* __restrict__ Bl,
                  float* __restrict__ C, int N, int K)
{
    extern __shared__ char dsm[];
    const uint32_t sb = smem_u32(dsm);
    const int tid = threadIdx.x;
    const int wid = tid >> 5, lane = tid & 31;
    const int warp_m = wid >> 2, warp_n = wid & 3;
    const int row0 = blockIdx.y * 128;
    const int col0 = blockIdx.x * 128;

    // copy coords: idx = tid + t*256; row = idx>>3 (0..127), u = idx&7 (16B unit)
    const int crow = tid >> 3;
    const int cu = tid & 7;

    // ldmatrix lane coords
    const int r16 = lane & 15;
    const int khB = (lane >> 4) * 16;           // 0 or 16 bytes
    const int a_row = warp_m * 64 + r16;
    const int b_row = warp_n * 32 + r16;

    float d[4][4][4];
#pragma unroll
    for (int mf = 0; mf < 4; mf++)
#pragma unroll
        for (int nf = 0; nf < 4; nf++)
#pragma unroll
            for (int j = 0; j < 4; j++) d[mf][nf][j] = 0.f;

    const int nch = K >> 6;

    // issue chunk 0
    {
        uint32_t s0 = sb;                        // buffer 0
#pragma unroll
        for (int t = 0; t < 4; t++) {
            int row = crow + t * 32;
            uint32_t so = SMEM_SWZ((uint32_t)(row * 128 + cu * 16));
            size_t ga = (size_t)(row0 + row) * K + cu * 8;
            size_t gb = (size_t)(col0 + row) * K + cu * 8;
            CP_ASYNC16(s0 + so,         (const char*)(Ah + ga));
            CP_ASYNC16(s0 + 16384 + so, (const char*)(Al + ga));
            CP_ASYNC16(s0 + 32768 + so, (const char*)(Bh + gb));
            CP_ASYNC16(s0 + 49152 + so, (const char*)(Bl + gb));
        }
        CP_COMMIT();
    }

    for (int c = 0; c < nch; c++) {
        if (c + 1 < nch) {
            uint32_t s1 = sb + ((c + 1) & 1) * 65536;
            const int ke = (c + 1) * 64;
#pragma unroll
            for (int t = 0; t < 4; t++) {
                int row = crow + t * 32;
                uint32_t so = SMEM_SWZ((uint32_t)(row * 128 + cu * 16));
                size_t ga = (size_t)(row0 + row) * K + ke + cu * 8;
                size_t gb = (size_t)(col0 + row) * K + ke + cu * 8;
                CP_ASYNC16(s1 + so,         (const char*)(Ah + ga));
                CP_ASYNC16(s1 + 16384 + so, (const char*)(Al + ga));
                CP_ASYNC16(s1 + 32768 + so, (const char*)(Bh + gb));
                CP_ASYNC16(s1 + 49152 + so, (const char*)(Bl + gb));
            }
            CP_COMMIT();
            CP_WAIT1();
        } else {
            CP_WAIT0();
        }
        __syncthreads();

        const uint32_t buf = sb + (c & 1) * 65536;
#pragma unroll
        for (int ks = 0; ks < 4; ks++) {
            uint32_t ah[4][4], al[4][4], bh[2][4], bl[2][4];
#pragma unroll
            for (int mf = 0; mf < 4; mf++) {
                uint32_t off = SMEM_SWZ((uint32_t)((a_row + mf * 16) * 128 + ks * 32 + khB));
                LDSM4(ah[mf], buf + off);
                LDSM4(al[mf], buf + 16384 + off);
            }
#pragma unroll
            for (int np = 0; np < 2; np++) {
                uint32_t off = SMEM_SWZ((uint32_t)((b_row + np * 16) * 128 + ks * 32 + khB));
                LDSM4(bh[np], buf + 32768 + off);
                LDSM4(bl[np], buf + 49152 + off);
            }
#pragma unroll
            for (int mf = 0; mf < 4; mf++)
#pragma unroll
                for (int nf = 0; nf < 4; nf++) {
                    const int np = nf >> 1, h = nf & 1;
                    MMA16816(d[mf][nf], ah[mf], bh[np][h], bh[np][2 + h]);
                    MMA16816(d[mf][nf], ah[mf], bl[np][h], bl[np][2 + h]);
                    MMA16816(d[mf][nf], al[mf], bh[np][h], bh[np][2 + h]);
                }
        }
        __syncthreads();
    }

    // epilogue: fragment layout -> C
    const int g = lane >> 2, tig = lane & 3;
#pragma unroll
    for (int mf = 0; mf < 4; mf++)
#pragma unroll
        for (int nf = 0; nf < 4; nf++) {
            int row = row0 + warp_m * 64 + mf * 16 + g;
            int col = col0 + warp_n * 32 + nf * 8 + tig * 2;
            *(float2*)&C[(size_t)row * N + col] = make_float2(d[mf][nf][0], d[mf][nf][1]);
            *(float2*)&C[(size_t)(row + 8) * N + col] = make_float2(d[mf][nf][2], d[mf][nf][3]);
        }
}

// ------------------- RoPE table (fp64 sincos once per (s,d)) -------------------
__global__ void rope_table_kernel(const int* __restrict__ pos_ids) {
    int s = blockIdx.x, d = threadIdx.x;
    double inv = pow(1000000.0, -(double)d / 64.0);
    double ang = (double)pos_ids[s] * inv;
    double sd, cd; sincos(ang, &sd, &cd);
    g_cos[s * 64 + d] = (float)cd;
    g_sin[s * 64 + d] = (float)sd;
}

// ------------------- RoPE apply + transpose to d-major -------------------
__global__ __launch_bounds__(256) void rope_t_kernel(
    const float* __restrict__ src, float* __restrict__ dst, int src_stride, float sc)
{
    __shared__ float T[32 * 129];
    const int s0 = blockIdx.x * 32;
    const int h = blockIdx.y;
    const int tid = threadIdx.x;
#pragma unroll
    for (int i = 0; i < 16; i++) {
        int idx = tid + i * 256;
        int sl = idx >> 7, d = idx & 127;
        T[sl * 129 + d] = src[(size_t)(s0 + sl) * src_stride + h * HDv + d];
    }
    __syncthreads();
#pragma unroll
    for (int i = 0; i < 8; i++) {
        int idx = tid + i * 256;
        int sl = idx >> 6, d = idx & 63;
        float c  = g_cos[(s0 + sl) * 64 + d];
        float sn = g_sin[(s0 + sl) * 64 + d];
        float x0 = T[sl * 129 + d], x1 = T[sl * 129 + d + 64];
        T[sl * 129 + d]      = (x0 * c - x1 * sn) * sc;
        T[sl * 129 + d + 64] = (x1 * c + x0 * sn) * sc;
    }
    __syncthreads();
#pragma unroll
    for (int i = 0; i < 16; i++) {
        int idx = tid + i * 256;
        int d = idx >> 5, sl = idx & 31;
        dst[(size_t)(h * HDv + d) * S_LEN + s0 + sl] = T[sl * 129 + d];
    }
}

// ------------------- Flash attention (causal, GQA), fp32 scalar -------------------
#define FA_SMEM_FLOATS (128*64 + 128*64 + 64*128 + 64*66)

__global__ __launch_bounds__(256) void flash_kernel() {
    extern __shared__ float sm[];
    float* QT = sm;
    float* KT = QT + 128 * 64;
    float* VS = KT + 128 * 64;
    float* PS = VS + 64 * 128;

    const int h  = blockIdx.y;
    const int qb = (int)gridDim.x - 1 - (int)blockIdx.x;
    const int q0 = qb * 64;
    const int kvh = h >> 2;
    const int tid = threadIdx.x;
    const int tx = tid & 15, ty = tid >> 4;

    const float* qtg = g_qt + (size_t)h * HDv * S_LEN;
    const float* ktg = g_kt + (size_t)kvh * HDv * S_LEN;
    const float* vg  = g_v + kvh * HDv;

#pragma unroll
    for (int it = 0; it < 8; it++) {
        int idx = tid + it * 256;
        int d = idx >> 4, m4 = (idx & 15) << 2;
        *(float4*)&QT[d * 64 + m4] = *(const float4*)&qtg[(size_t)d * S_LEN + q0 + m4];
    }

    float m_run[4], l_run[4], acc_o[4][8];
#pragma unroll
    for (int i = 0; i < 4; i++) {
        m_run[i] = -1e30f; l_run[i] = 0.f;
#pragma unroll
        for (int j = 0; j < 8; j++) acc_o[i][j] = 0.f;
    }
    __syncthreads();

    for (int kb = 0; kb <= qb; kb++) {
        const int k0 = kb * 64;
#pragma unroll
        for (int it = 0; it < 8; it++) {
            int idx = tid + it * 256;
            int d = idx >> 4, n4 = (idx & 15) << 2;
            *(float4*)&KT[d * 64 + n4] = *(const float4*)&ktg[(size_t)d * S_LEN + k0 + n4];
        }
#pragma unroll
        for (int it = 0; it < 8; it++) {
            int idx = tid + it * 256;
            int n = idx >> 5, d4 = (idx & 31) << 2;
            *(float4*)&VS[n * 128 + d4] =
                *(const float4*)&vg[(size_t)(k0 + n) * KVD + d4];
        }
        __syncthreads();

        float s_acc[4][4];
#pragma unroll
        for (int i = 0; i < 4; i++)
#pragma unroll
            for (int j = 0; j < 4; j++) s_acc[i][j] = 0.f;
#pragma unroll 8
        for (int kk = 0; kk < 128; kk++) {
            float4 a = *(const float4*)&QT[kk * 64 + ty * 4];
            float4 b = *(const float4*)&KT[kk * 64 + tx * 4];
            float av[4] = {a.x, a.y, a.z, a.w};
            float bv[4] = {b.x, b.y, b.z, b.w};
#pragma unroll
            for (int i = 0; i < 4; i++)
#pragma unroll
                for (int j = 0; j < 4; j++)
                    s_acc[i][j] = fmaf(av[i], bv[j], s_acc[i][j]);
        }

        if (kb == qb) {
#pragma unroll
            for (int i = 0; i < 4; i++)
#pragma unroll
                for (int j = 0; j < 4; j++)
                    if (tx * 4 + j > ty * 4 + i) s_acc[i][j] = -1e30f;
        }

#pragma unroll
        for (int i = 0; i < 4; i++) {
            float mv = fmaxf(fmaxf(s_acc[i][0], s_acc[i][1]),
                             fmaxf(s_acc[i][2], s_acc[i][3]));
#pragma unroll
            for (int o = 1; o < 16; o <<= 1)
                mv = fmaxf(mv, __shfl_xor_sync(0xffffffffu, mv, o));
            float m_new = fmaxf(m_run[i], mv);
            float fs = __expf(m_run[i] - m_new);
            float sum = 0.f;
#pragma unroll
            for (int j = 0; j < 4; j++) {
                float p = __expf(s_acc[i][j] - m_new);
                s_acc[i][j] = p; sum += p;
            }
#pragma unroll
            for (int o = 1; o < 16; o <<= 1)
                sum += __shfl_xor_sync(0xffffffffu, sum, o);
            m_run[i] = m_new;
            l_run[i] = l_run[i] * fs + sum;
#pragma unroll
            for (int j = 0; j < 8; j++) acc_o[i][j] *= fs;
#pragma unroll
            for (int j = 0; j < 4; j++)
                PS[(ty * 4 + i) * 66 + tx * 4 + j] = s_acc[i][j];
        }
        __syncthreads();

#pragma unroll 4
        for (int kk = 0; kk < 64; kk++) {
            float4 b0 = *(const float4*)&VS[kk * 128 + tx * 8];
            float4 b1 = *(const float4*)&VS[kk * 128 + tx * 8 + 4];
#pragma unroll
            for (int i = 0; i < 4; i++) {
                float p = PS[(ty * 4 + i) * 66 + kk];
                acc_o[i][0] = fmaf(p, b0.x, acc_o[i][0]);
                acc_o[i][1] = fmaf(p, b0.y, acc_o[i][1]);
                acc_o[i][2] = fmaf(p, b0.z, acc_o[i][2]);
                acc_o[i][3] = fmaf(p, b0.w, acc_o[i][3]);
                acc_o[i][4] = fmaf(p, b1.x, acc_o[i][4]);
                acc_o[i][5] = fmaf(p, b1.y, acc_o[i][5]);
                acc_o[i][6] = fmaf(p, b1.z, acc_o[i][6]);
                acc_o[i][7] = fmaf(p, b1.w, acc_o[i][7]);
            }
        }
        __syncthreads();
    }

#pragma unroll
    for (int i = 0; i < 4; i++) {
        int r = q0 + ty * 4 + i;
        float inv = 1.f / l_run[i];
        float4 o0 = make_float4(acc_o[i][0]*inv, acc_o[i][1]*inv, acc_o[i][2]*inv, acc_o[i][3]*inv);
        float4 o1 = make_float4(acc_o[i][4]*inv, acc_o[i][5]*inv, acc_o[i][6]*inv, acc_o[i][7]*inv);
        float* dst = g_ao + (size_t)r * EMB + h * HDv + tx * 8;
        *(float4*)dst = o0;
        *(float4*)(dst + 4) = o1;
    }
}

// ------------------- launch -------------------
extern "C" void kernel_launch(void* const* d_in, const int* in_sizes, int n_in,
                              void* d_out, int out_size)
{
    const float* hs = (const float*)d_in[0];
    const float* Wq = (const float*)d_in[1];
    const float* Wk = (const float*)d_in[2];
    const float* Wv = (const float*)d_in[3];
    const float* Wo = (const float*)d_in[4];
    const int*   pos = (const int*)d_in[6];
    float* out = (float*)d_out;

    float *p_q, *p_k, *p_v, *p_ao, *p_qt, *p_kt;
    cudaGetSymbolAddress((void**)&p_q,  g_q);
    cudaGetSymbolAddress((void**)&p_k,  g_k);
    cudaGetSymbolAddress((void**)&p_v,  g_v);
    cudaGetSymbolAddress((void**)&p_ao, g_ao);
    cudaGetSymbolAddress((void**)&p_qt, g_qt);
    cudaGetSymbolAddress((void**)&p_kt, g_kt);
    __nv_bfloat16 *p_ah, *p_al, *p_aoh, *p_aol;
    __nv_bfloat16 *p_wqh, *p_wql, *p_wkh, *p_wkl, *p_wvh, *p_wvl, *p_woh, *p_wol;
    cudaGetSymbolAddress((void**)&p_ah,  g_ah);
    cudaGetSymbolAddress((void**)&p_al,  g_al);
    cudaGetSymbolAddress((void**)&p_aoh, g_aoh);
    cudaGetSymbolAddress((void**)&p_aol, g_aol);
    cudaGetSymbolAddress((void**)&p_wqh, g_wqh);
    cudaGetSymbolAddress((void**)&p_wql, g_wql);
    cudaGetSymbolAddress((void**)&p_wkh, g_wkh);
    cudaGetSymbolAddress((void**)&p_wkl, g_wkl);
    cudaGetSymbolAddress((void**)&p_wvh, g_wvh);
    cudaGetSymbolAddress((void**)&p_wvl, g_wvl);
    cudaGetSymbolAddress((void**)&p_woh, g_woh);
    cudaGetSymbolAddress((void**)&p_wol, g_wol);

    cudaFuncSetAttribute(flash_kernel, cudaFuncAttributeMaxDynamicSharedMemorySize,
                         FA_SMEM_FLOATS * sizeof(float));
    cudaFuncSetAttribute(tgemm_kernel, cudaFuncAttributeMaxDynamicSharedMemorySize, TG_SMEM);

    // 0) split conversions (A once; weights transposed+split)
    conv_split_kernel<<<(S_LEN * EMB / 4 + 255) / 256, 256>>>(hs, p_ah, p_al, S_LEN * EMB / 4);
    conv_split_t_kernel<<<dim3(EMB / 32, EMB / 32), dim3(32, 8)>>>(Wq, p_wqh, p_wql, EMB, EMB);
    conv_split_t_kernel<<<dim3(KVD / 32, EMB / 32), dim3(32, 8)>>>(Wk, p_wkh, p_wkl, EMB, KVD);
    conv_split_t_kernel<<<dim3(KVD / 32, EMB / 32), dim3(32, 8)>>>(Wv, p_wvh, p_wvl, EMB, KVD);
    conv_split_t_kernel<<<dim3(EMB / 32, EMB / 32), dim3(32, 8)>>>(Wo, p_woh, p_wol, EMB, EMB);

    // 1) projections on HMMA tensor cores (split-bf16, fp32-accurate)
    tgemm_kernel<<<dim3(EMB / 128, S_LEN / 128), 256, TG_SMEM>>>(p_ah, p_al, p_wqh, p_wql, p_q, EMB, EMB);
    tgemm_kernel<<<dim3(KVD / 128, S_LEN / 128), 256, TG_SMEM>>>(p_ah, p_al, p_wkh, p_wkl, p_k, KVD, EMB);
    tgemm_kernel<<<dim3(KVD / 128, S_LEN / 128), 256, TG_SMEM>>>(p_ah, p_al, p_wvh, p_wvl, p_v, KVD, EMB);

    // 2) RoPE
    rope_table_kernel<<<S_LEN, 64>>>(pos);
    rope_t_kernel<<<dim3(S_LEN / 32, NHEADS), 256>>>(p_q, p_qt, EMB, 0.08838834764831845f);
    rope_t_kernel<<<dim3(S_LEN / 32, NKVH),  256>>>(p_k, p_kt, KVD, 1.0f);

    // 3) causal flash attention (fp32 scalar this round)
    flash_kernel<<<dim3(S_LEN / 64, NHEADS), 256, FA_SMEM_FLOATS * sizeof(float)>>>();

    // 4) output projection on HMMA tensor cores
    conv_split_kernel<<<(S_LEN * EMB / 4 + 255) / 256, 256>>>(p_ao, p_aoh, p_aol, S_LEN * EMB / 4);
    tgemm_kernel<<<dim3(EMB / 128, S_LEN / 128), 256, TG_SMEM>>>(p_aoh, p_aol, p_woh, p_wol, out, EMB, EMB);
}

// round 8
// speedup vs baseline: 3.3042x; 1.8781x over previous
#include <cuda_runtime.h>
#include <cuda_bf16.h>
#include <math.h>
#include <stdint.h>

#define S_LEN 4096
#define EMB   2048
#define NHEADS 16
#define NKVH   4
#define HDv    128
#define KVD    (NKVH * HDv)   // 512

// ------------------- scratch (device globals; no allocations) -------------------
__device__ float g_q [S_LEN * EMB];
__device__ float g_k [S_LEN * KVD];
__device__ float g_v [S_LEN * KVD];
__device__ float g_ao[S_LEN * EMB];
__device__ float g_cos[S_LEN * 64];
__device__ float g_sin[S_LEN * 64];
// split-bf16 operands (GEMM)
__device__ __nv_bfloat16 g_ah [S_LEN * EMB], g_al [S_LEN * EMB];
__device__ __nv_bfloat16 g_aoh[S_LEN * EMB], g_aol[S_LEN * EMB];
__device__ __nv_bfloat16 g_wqh[EMB * EMB], g_wql[EMB * EMB];
__device__ __nv_bfloat16 g_wkh[KVD * EMB], g_wkl[KVD * EMB];
__device__ __nv_bfloat16 g_wvh[KVD * EMB], g_wvl[KVD * EMB];
__device__ __nv_bfloat16 g_woh[EMB * EMB], g_wol[EMB * EMB];
// split-bf16 attention operands
__device__ __nv_bfloat16 g_qh [NHEADS * S_LEN * HDv], g_ql [NHEADS * S_LEN * HDv]; // [h][s][d]
__device__ __nv_bfloat16 g_kh [NKVH * S_LEN * HDv],   g_klo[NKVH * S_LEN * HDv];   // [kvh][s][d]
__device__ __nv_bfloat16 g_vth[NKVH * HDv * S_LEN],   g_vtl[NKVH * HDv * S_LEN];   // [kvh][d][s]

// ------------------- helpers -------------------
__device__ __forceinline__ uint32_t smem_u32(const void* p) {
    uint32_t a;
    asm("{ .reg .u64 t; cvta.to.shared.u64 t, %1; cvt.u32.u64 %0, t; }" : "=r"(a) : "l"(p));
    return a;
}
#define SMEM_SWZ(off) ((off) ^ (((off) >> 3) & 0x70))

#define LDSM4(r, a) \
    asm volatile("ldmatrix.sync.aligned.m8n8.x4.shared.b16 {%0,%1,%2,%3}, [%4];" \
        : "=r"((r)[0]), "=r"((r)[1]), "=r"((r)[2]), "=r"((r)[3]) : "r"(a))

#define MMA16816(d, a, b0v, b1v) \
    asm volatile("mma.sync.aligned.m16n8k16.row.col.f32.bf16.bf16.f32 " \
        "{%0,%1,%2,%3}, {%4,%5,%6,%7}, {%8,%9}, {%0,%1,%2,%3};" \
        : "+f"((d)[0]), "+f"((d)[1]), "+f"((d)[2]), "+f"((d)[3]) \
        : "r"((a)[0]), "r"((a)[1]), "r"((a)[2]), "r"((a)[3]), "r"(b0v), "r"(b1v))

#define CP_ASYNC16(s, g) \
    asm volatile("cp.async.cg.shared.global [%0], [%1], 16;" :: "r"(s), "l"(g))
#define CP_COMMIT() asm volatile("cp.async.commit_group;" ::: "memory")
#define CP_WAIT1()  asm volatile("cp.async.wait_group 1;" ::: "memory")
#define CP_WAIT0()  asm volatile("cp.async.wait_group 0;" ::: "memory")

// split a,b into packed bf16x2 hi and lo  (lower half = a, upper half = b)
__device__ __forceinline__ void split2(float a, float b, uint32_t& ph, uint32_t& pl) {
    float ha = __bfloat162float(__float2bfloat16(a));
    float hb = __bfloat162float(__float2bfloat16(b));
    asm("cvt.rn.bf16x2.f32 %0, %1, %2;" : "=r"(ph) : "f"(hb), "f"(ha));
    asm("cvt.rn.bf16x2.f32 %0, %1, %2;" : "=r"(pl) : "f"(b - hb), "f"(a - ha));
}

// ------------------- split conversion: fp32 -> (hi, lo) bf16 -------------------
__global__ __launch_bounds__(256) void conv_split_kernel(
    const float* __restrict__ src, __nv_bfloat16* __restrict__ hi,
    __nv_bfloat16* __restrict__ lo, int n4)
{
    int i = blockIdx.x * 256 + threadIdx.x;
    if (i >= n4) return;
    float4 v = ((const float4*)src)[i];
    __nv_bfloat16 h0 = __float2bfloat16(v.x), h1 = __float2bfloat16(v.y);
    __nv_bfloat16 h2 = __float2bfloat16(v.z), h3 = __float2bfloat16(v.w);
    __nv_bfloat16 l0 = __float2bfloat16(v.x - __bfloat162float(h0));
    __nv_bfloat16 l1 = __float2bfloat16(v.y - __bfloat162float(h1));
    __nv_bfloat16 l2 = __float2bfloat16(v.z - __bfloat162float(h2));
    __nv_bfloat16 l3 = __float2bfloat16(v.w - __bfloat162float(h3));
    ((__nv_bfloat162*)hi)[i * 2]     = __nv_bfloat162(h0, h1);
    ((__nv_bfloat162*)hi)[i * 2 + 1] = __nv_bfloat162(h2, h3);
    ((__nv_bfloat162*)lo)[i * 2]     = __nv_bfloat162(l0, l1);
    ((__nv_bfloat162*)lo)[i * 2 + 1] = __nv_bfloat162(l2, l3);
}

// transpose + split: src [R',C] fp32 (rows indexed with stride C) -> hi/lo [C,R] bf16
__global__ __launch_bounds__(256) void conv_split_t_kernel(
    const float* __restrict__ src, __nv_bfloat16* __restrict__ hi,
    __nv_bfloat16* __restrict__ lo, int R, int C)
{
    __shared__ float T[32][33];
    const int x = threadIdx.x, y = threadIdx.y;     // block (32, 8)
    const int c0 = blockIdx.x * 32, r0 = blockIdx.y * 32;
#pragma unroll
    for (int i = 0; i < 4; i++)
        T[y + 8 * i][x] = src[(size_t)(r0 + y + 8 * i) * C + c0 + x];
    __syncthreads();
#pragma unroll
    for (int i = 0; i < 4; i++) {
        int r = y + 8 * i;
        float v = T[x][r];
        __nv_bfloat16 h = __float2bfloat16(v);
        __nv_bfloat16 l = __float2bfloat16(v - __bfloat162float(h));
        size_t o = (size_t)(c0 + r) * R + r0 + x;
        hi[o] = h; lo[o] = l;
    }
}

// ------------------- mma.sync split-bf16 GEMM (verified R7) -------------------
#define TG_SMEM (2 * 65536)

__global__ __launch_bounds__(256, 1)
void tgemm_kernel(const __nv_bfloat16* __restrict__ Ah, const __nv_bfloat16* __restrict__ Al,
                  const __nv_bfloat16* __restrict__ Bh, const __nv_bfloat16* __restrict__ Bl,
                  float* __restrict__ C, int N, int K)
{
    extern __shared__ char dsm[];
    const uint32_t sb = smem_u32(dsm);
    const int tid = threadIdx.x;
    const int wid = tid >> 5, lane = tid & 31;
    const int warp_m = wid >> 2, warp_n = wid & 3;
    const int row0 = blockIdx.y * 128;
    const int col0 = blockIdx.x * 128;

    const int crow = tid >> 3;
    const int cu = tid & 7;

    const int r16 = lane & 15;
    const int khB = (lane >> 4) * 16;
    const int a_row = warp_m * 64 + r16;
    const int b_row = warp_n * 32 + r16;

    float d[4][4][4];
#pragma unroll
    for (int mf = 0; mf < 4; mf++)
#pragma unroll
        for (int nf = 0; nf < 4; nf++)
#pragma unroll
            for (int j = 0; j < 4; j++) d[mf][nf][j] = 0.f;

    const int nch = K >> 6;

    {
        uint32_t s0 = sb;
#pragma unroll
        for (int t = 0; t < 4; t++) {
            int row = crow + t * 32;
            uint32_t so = SMEM_SWZ((uint32_t)(row * 128 + cu * 16));
            size_t ga = (size_t)(row0 + row) * K + cu * 8;
            size_t gb = (size_t)(col0 + row) * K + cu * 8;
            CP_ASYNC16(s0 + so,         (const char*)(Ah + ga));
            CP_ASYNC16(s0 + 16384 + so, (const char*)(Al + ga));
            CP_ASYNC16(s0 + 32768 + so, (const char*)(Bh + gb));
            CP_ASYNC16(s0 + 49152 + so, (const char*)(Bl + gb));
        }
        CP_COMMIT();
    }

    for (int c = 0; c < nch; c++) {
        if (c + 1 < nch) {
            uint32_t s1 = sb + ((c + 1) & 1) * 65536;
            const int ke = (c + 1) * 64;
#pragma unroll
            for (int t = 0; t < 4; t++) {
                int row = crow + t * 32;
                uint32_t so = SMEM_SWZ((uint32_t)(row * 128 + cu * 16));
                size_t ga = (size_t)(row0 + row) * K + ke + cu * 8;
                size_t gb = (size_t)(col0 + row) * K + ke + cu * 8;
                CP_ASYNC16(s1 + so,         (const char*)(Ah + ga));
                CP_ASYNC16(s1 + 16384 + so, (const char*)(Al + ga));
                CP_ASYNC16(s1 + 32768 + so, (const char*)(Bh + gb));
                CP_ASYNC16(s1 + 49152 + so, (const char*)(Bl + gb));
            }
            CP_COMMIT();
            CP_WAIT1();
        } else {
            CP_WAIT0();
        }
        __syncthreads();

        const uint32_t buf = sb + (c & 1) * 65536;
#pragma unroll
        for (int ks = 0; ks < 4; ks++) {
            uint32_t ah[4][4], al[4][4], bh[2][4], bl[2][4];
#pragma unroll
            for (int mf = 0; mf < 4; mf++) {
                uint32_t off = SMEM_SWZ((uint32_t)((a_row + mf * 16) * 128 + ks * 32 + khB));
                LDSM4(ah[mf], buf + off);
                LDSM4(al[mf], buf + 16384 + off);
            }
#pragma unroll
            for (int np = 0; np < 2; np++) {
                uint32_t off = SMEM_SWZ((uint32_t)((b_row + np * 16) * 128 + ks * 32 + khB));
                LDSM4(bh[np], buf + 32768 + off);
                LDSM4(bl[np], buf + 49152 + off);
            }
#pragma unroll
            for (int mf = 0; mf < 4; mf++)
#pragma unroll
                for (int nf = 0; nf < 4; nf++) {
                    const int np = nf >> 1, h = nf & 1;
                    MMA16816(d[mf][nf], ah[mf], bh[np][h], bh[np][2 + h]);
                    MMA16816(d[mf][nf], ah[mf], bl[np][h], bl[np][2 + h]);
                    MMA16816(d[mf][nf], al[mf], bh[np][h], bh[np][2 + h]);
                }
        }
        __syncthreads();
    }

    const int g = lane >> 2, tig = lane & 3;
#pragma unroll
    for (int mf = 0; mf < 4; mf++)
#pragma unroll
        for (int nf = 0; nf < 4; nf++) {
            int row = row0 + warp_m * 64 + mf * 16 + g;
            int col = col0 + warp_n * 32 + nf * 8 + tig * 2;
            *(float2*)&C[(size_t)row * N + col] = make_float2(d[mf][nf][0], d[mf][nf][1]);
            *(float2*)&C[(size_t)(row + 8) * N + col] = make_float2(d[mf][nf][2], d[mf][nf][3]);
        }
}

// ------------------- RoPE table (fp64 sincos once per (s,d)) -------------------
__global__ void rope_table_kernel(const int* __restrict__ pos_ids) {
    int s = blockIdx.x, d = threadIdx.x;
    double inv = pow(1000000.0, -(double)d / 64.0);
    double ang = (double)pos_ids[s] * inv;
    double sd, cd; sincos(ang, &sd, &cd);
    g_cos[s * 64 + d] = (float)cd;
    g_sin[s * 64 + d] = (float)sd;
}

// ------------------- RoPE apply + split to bf16 hi/lo [h][s][d] -------------------
__global__ void rope_split_kernel(const float* __restrict__ src,
                                  __nv_bfloat16* __restrict__ oh,
                                  __nv_bfloat16* __restrict__ ol,
                                  int ncols, float sc)
{
    int s = blockIdx.x, h = blockIdx.y, d = threadIdx.x;  // d in [0,64)
    float c  = g_cos[s * 64 + d];
    float sn = g_sin[s * 64 + d];
    const float* p = src + (size_t)s * ncols + h * HDv;
    float x0 = p[d], x1 = p[d + 64];
    float y0 = (x0 * c - x1 * sn) * sc;
    float y1 = (x1 * c + x0 * sn) * sc;
    size_t o = ((size_t)h * S_LEN + s) * HDv + d;
    __nv_bfloat16 h0 = __float2bfloat16(y0);
    __nv_bfloat16 h1 = __float2bfloat16(y1);
    oh[o] = h0;      ol[o]      = __float2bfloat16(y0 - __bfloat162float(h0));
    oh[o + 64] = h1; ol[o + 64] = __float2bfloat16(y1 - __bfloat162float(h1));
}

// ------------------- Flash attention: mma.sync split-bf16 -------------------
// CTA: 64 q-rows x one head; 8 warps: wm=wid>>1 (16 q-rows), wn=wid&1 (kv split 32).
// K-blocks of 64 kv, double-buffered cp.async.
// smem bytes: Qh 0..17408, Ql ..34816 (pitch 272);
//   K bufs at 34816 (2 x [Kh 17408 | Kl 17408], pitch 272);
//   VT bufs at 104448 (2 x [Vh 18432 | Vl 18432], pitch 144, rows=d);
//   red at 178176 (2 x 128 floats). Epilogue O-staging reuses K region.
#define FQOFF  0
#define FQLOFF 17408
#define FKOFF  34816
#define FVOFF  104448
#define FREDOFF 178176
#define FA2_SMEM 179200

__global__ __launch_bounds__(256, 1) void flash_mma_kernel() {
    extern __shared__ char fsm[];
    const uint32_t sb = smem_u32(fsm);
    const int tid = threadIdx.x;
    const int wid = tid >> 5, lane = tid & 31;
    const int wm = wid >> 1, wn = wid & 1;
    const int g = lane >> 2, tig = lane & 3;
    const int r16 = lane & 15;
    const int khB = (lane >> 4) * 16;
    const int h = blockIdx.y;
    const int qb = (int)gridDim.x - 1 - (int)blockIdx.x;
    const int q0 = qb * 64;
    const int kvh = h >> 2;

    const char* qhp = (const char*)(g_qh  + ((size_t)h * S_LEN + q0) * HDv);
    const char* qlp = (const char*)(g_ql  + ((size_t)h * S_LEN + q0) * HDv);
    const char* khp = (const char*)(g_kh  + (size_t)kvh * S_LEN * HDv);
    const char* klp = (const char*)(g_klo + (size_t)kvh * S_LEN * HDv);
    const char* vhp = (const char*)(g_vth + (size_t)kvh * HDv * S_LEN);
    const char* vlp = (const char*)(g_vtl + (size_t)kvh * HDv * S_LEN);

    // Q tile + KV block 0, one commit group
#pragma unroll
    for (int t = 0; t < 4; t++) {
        int idx = tid + t * 256;
        int row = idx >> 4, u = idx & 15;
        CP_ASYNC16(sb + FQOFF  + row * 272 + u * 16, qhp + row * 256 + u * 16);
        CP_ASYNC16(sb + FQLOFF + row * 272 + u * 16, qlp + row * 256 + u * 16);
        CP_ASYNC16(sb + FKOFF + row * 272 + u * 16,         khp + row * 256 + u * 16);
        CP_ASYNC16(sb + FKOFF + 17408 + row * 272 + u * 16, klp + row * 256 + u * 16);
        int vr = idx >> 3, vu = idx & 7;
        CP_ASYNC16(sb + FVOFF + vr * 144 + vu * 16,         vhp + (size_t)vr * (S_LEN * 2) + vu * 16);
        CP_ASYNC16(sb + FVOFF + 18432 + vr * 144 + vu * 16, vlp + (size_t)vr * (S_LEN * 2) + vu * 16);
    }
    CP_COMMIT();

    float m_run[2] = {-1e30f, -1e30f};
    float l_run[2] = {0.f, 0.f};
    float o[16][4];
#pragma unroll
    for (int i = 0; i < 16; i++) { o[i][0] = o[i][1] = o[i][2] = o[i][3] = 0.f; }

    float* redA = (float*)(fsm + FREDOFF);
    float* redB = redA + 128;
    const int row0 = wm * 16 + g;
    const int nkb = qb + 1;

    for (int kb = 0; kb < nkb; kb++) {
        if (kb + 1 < nkb) {
            const size_t k0 = (size_t)(kb + 1) * 64;
            uint32_t KB = sb + FKOFF + ((kb + 1) & 1) * 34816;
            uint32_t VB = sb + FVOFF + ((kb + 1) & 1) * 36864;
#pragma unroll
            for (int t = 0; t < 4; t++) {
                int idx = tid + t * 256;
                int row = idx >> 4, u = idx & 15;
                CP_ASYNC16(KB + row * 272 + u * 16,         khp + (k0 + row) * 256 + u * 16);
                CP_ASYNC16(KB + 17408 + row * 272 + u * 16, klp + (k0 + row) * 256 + u * 16);
                int vr = idx >> 3, vu = idx & 7;
                CP_ASYNC16(VB + vr * 144 + vu * 16,         vhp + (size_t)vr * (S_LEN * 2) + k0 * 2 + vu * 16);
                CP_ASYNC16(VB + 18432 + vr * 144 + vu * 16, vlp + (size_t)vr * (S_LEN * 2) + k0 * 2 + vu * 16);
            }
            CP_COMMIT();
            CP_WAIT1();
        } else {
            CP_WAIT0();
        }
        __syncthreads();

        const uint32_t KB = sb + FKOFF + (kb & 1) * 34816;
        const uint32_t VB = sb + FVOFF + (kb & 1) * 36864;

        // ---- S = Q K^T (split 3-pass) ----
        float s[4][4];
#pragma unroll
        for (int nf = 0; nf < 4; nf++) s[nf][0] = s[nf][1] = s[nf][2] = s[nf][3] = 0.f;
#pragma unroll
        for (int ks = 0; ks < 8; ks++) {
            uint32_t aqh[4], aql[4], bkh[2][4], bkl[2][4];
            uint32_t qo = (uint32_t)((wm * 16 + r16) * 272 + ks * 32 + khB);
            LDSM4(aqh, sb + FQOFF + qo);
            LDSM4(aql, sb + FQLOFF + qo);
#pragma unroll
            for (int np = 0; np < 2; np++) {
                uint32_t ko = (uint32_t)((wn * 32 + np * 16 + r16) * 272 + ks * 32 + khB);
                LDSM4(bkh[np], KB + ko);
                LDSM4(bkl[np], KB + 17408 + ko);
            }
#pragma unroll
            for (int nf = 0; nf < 4; nf++) {
                const int np = nf >> 1, hs = nf & 1;
                MMA16816(s[nf], aqh, bkh[np][hs], bkh[np][2 + hs]);
                MMA16816(s[nf], aqh, bkl[np][hs], bkl[np][2 + hs]);
                MMA16816(s[nf], aql, bkh[np][hs], bkh[np][2 + hs]);
            }
        }

        if (kb == qb) {  // causal mask on diagonal block
#pragma unroll
            for (int nf = 0; nf < 4; nf++)
#pragma unroll
                for (int j = 0; j < 4; j++) {
                    int r = wm * 16 + g + ((j >> 1) << 3);
                    int c = wn * 32 + nf * 8 + tig * 2 + (j & 1);
                    if (c > r) s[nf][j] = -1e30f;
                }
        }

        // ---- online softmax (quad shfl + cross-wn smem) ----
        float rmx0 = -1e30f, rmx1 = -1e30f;
#pragma unroll
        for (int nf = 0; nf < 4; nf++) {
            rmx0 = fmaxf(rmx0, fmaxf(s[nf][0], s[nf][1]));
            rmx1 = fmaxf(rmx1, fmaxf(s[nf][2], s[nf][3]));
        }
        rmx0 = fmaxf(rmx0, __shfl_xor_sync(0xffffffffu, rmx0, 1));
        rmx0 = fmaxf(rmx0, __shfl_xor_sync(0xffffffffu, rmx0, 2));
        rmx1 = fmaxf(rmx1, __shfl_xor_sync(0xffffffffu, rmx1, 1));
        rmx1 = fmaxf(rmx1, __shfl_xor_sync(0xffffffffu, rmx1, 2));
        redA[wn * 64 + row0] = rmx0;
        redA[wn * 64 + row0 + 8] = rmx1;
        __syncthreads();
        float mn0 = fmaxf(m_run[0], fmaxf(redA[row0],     redA[64 + row0]));
        float mn1 = fmaxf(m_run[1], fmaxf(redA[row0 + 8], redA[64 + row0 + 8]));
        float fs0 = __expf(m_run[0] - mn0);
        float fs1 = __expf(m_run[1] - mn1);
        m_run[0] = mn0; m_run[1] = mn1;

        float sum0 = 0.f, sum1 = 0.f;
#pragma unroll
        for (int nf = 0; nf < 4; nf++) {
            s[nf][0] = __expf(s[nf][0] - mn0);
            s[nf][1] = __expf(s[nf][1] - mn0);
            s[nf][2] = __expf(s[nf][2] - mn1);
            s[nf][3] = __expf(s[nf][3] - mn1);
            sum0 += s[nf][0] + s[nf][1];
            sum1 += s[nf][2] + s[nf][3];
        }
        sum0 += __shfl_xor_sync(0xffffffffu, sum0, 1);
        sum0 += __shfl_xor_sync(0xffffffffu, sum0, 2);
        sum1 += __shfl_xor_sync(0xffffffffu, sum1, 1);
        sum1 += __shfl_xor_sync(0xffffffffu, sum1, 2);
        redB[wn * 64 + row0] = sum0;
        redB[wn * 64 + row0 + 8] = sum1;
        __syncthreads();
        l_run[0] = l_run[0] * fs0 + redB[row0] + redB[64 + row0];
        l_run[1] = l_run[1] * fs1 + redB[row0 + 8] + redB[64 + row0 + 8];

        // rescale O
#pragma unroll
        for (int i = 0; i < 16; i++) {
            o[i][0] *= fs0; o[i][1] *= fs0; o[i][2] *= fs1; o[i][3] *= fs1;
        }

        // ---- P A-frags (register reuse, split hi/lo) ----
        uint32_t aph[2][4], apl[2][4];
#pragma unroll
        for (int kk = 0; kk < 2; kk++) {
            const int nfA = 2 * kk, nfB = 2 * kk + 1;
            split2(s[nfA][0], s[nfA][1], aph[kk][0], apl[kk][0]);
            split2(s[nfA][2], s[nfA][3], aph[kk][1], apl[kk][1]);
            split2(s[nfB][0], s[nfB][1], aph[kk][2], apl[kk][2]);
            split2(s[nfB][2], s[nfB][3], aph[kk][3], apl[kk][3]);
        }

        // ---- O += P V (split 3-pass); this warp covers kv k-steps 2wn, 2wn+1 ----
#pragma unroll
        for (int kk = 0; kk < 2; kk++) {
            const int ksv = 2 * wn + kk;
#pragma unroll
            for (int np = 0; np < 8; np++) {
                uint32_t bvh[4], bvl[4];
                uint32_t vo = (uint32_t)((np * 16 + r16) * 144 + ksv * 32 + khB);
                LDSM4(bvh, VB + vo);
                LDSM4(bvl, VB + 18432 + vo);
#pragma unroll
                for (int hs = 0; hs < 2; hs++) {
                    const int nd = np * 2 + hs;
                    MMA16816(o[nd], aph[kk], bvh[hs], bvh[2 + hs]);
                    MMA16816(o[nd], aph[kk], bvl[hs], bvl[2 + hs]);
                    MMA16816(o[nd], apl[kk], bvh[hs], bvh[2 + hs]);
                }
            }
        }
        __syncthreads();   // protect smem buffers before next iteration's issue
    }

    // ---- epilogue: combine wn partials, normalize, store ----
    float* OS = (float*)(fsm + FKOFF);   // reuse K region: 64 x 132 fp32
    if (wn == 0) {
#pragma unroll
        for (int nd = 0; nd < 16; nd++) {
            int c = nd * 8 + tig * 2;
            OS[row0 * 132 + c]           = o[nd][0];
            OS[row0 * 132 + c + 1]       = o[nd][1];
            OS[(row0 + 8) * 132 + c]     = o[nd][2];
            OS[(row0 + 8) * 132 + c + 1] = o[nd][3];
        }
    }
    __syncthreads();
    if (wn == 1) {
        float inv0 = 1.f / l_run[0], inv1 = 1.f / l_run[1];
        float* d0 = g_ao + (size_t)(q0 + row0) * EMB + h * HDv;
        float* d1 = g_ao + (size_t)(q0 + row0 + 8) * EMB + h * HDv;
#pragma unroll
        for (int nd = 0; nd < 16; nd++) {
            int c = nd * 8 + tig * 2;
            float a0 = (o[nd][0] + OS[row0 * 132 + c]) * inv0;
            float a1 = (o[nd][1] + OS[row0 * 132 + c + 1]) * inv0;
            float a2 = (o[nd][2] + OS[(row0 + 8) * 132 + c]) * inv1;
            float a3 = (o[nd][3] + OS[(row0 + 8) * 132 + c + 1]) * inv1;
            *(float2*)(d0 + c) = make_float2(a0, a1);
            *(float2*)(d1 + c) = make_float2(a2, a3);
        }
    }
}

// ------------------- launch -------------------
extern "C" void kernel_launch(void* const* d_in, const int* in_sizes, int n_in,
                              void* d_out, int out_size)
{
    const float* hs = (const float*)d_in[0];
    const float* Wq = (const float*)d_in[1];
    const float* Wk = (const float*)d_in[2];
    const float* Wv = (const float*)d_in[3];
    const float* Wo = (const float*)d_in[4];
    const int*   pos = (const int*)d_in[6];
    float* out = (float*)d_out;

    float *p_q, *p_k, *p_v, *p_ao;
    cudaGetSymbolAddress((void**)&p_q,  g_q);
    cudaGetSymbolAddress((void**)&p_k,  g_k);
    cudaGetSymbolAddress((void**)&p_v,  g_v);
    cudaGetSymbolAddress((void**)&p_ao, g_ao);
    __nv_bfloat16 *p_ah, *p_al, *p_aoh, *p_aol;
    __nv_bfloat16 *p_wqh, *p_wql, *p_wkh, *p_wkl, *p_wvh, *p_wvl, *p_woh, *p_wol;
    __nv_bfloat16 *p_qh, *p_ql, *p_kh, *p_klo, *p_vth, *p_vtl;
    cudaGetSymbolAddress((void**)&p_ah,  g_ah);
    cudaGetSymbolAddress((void**)&p_al,  g_al);
    cudaGetSymbolAddress((void**)&p_aoh, g_aoh);
    cudaGetSymbolAddress((void**)&p_aol, g_aol);
    cudaGetSymbolAddress((void**)&p_wqh, g_wqh);
    cudaGetSymbolAddress((void**)&p_wql, g_wql);
    cudaGetSymbolAddress((void**)&p_wkh, g_wkh);
    cudaGetSymbolAddress((void**)&p_wkl, g_wkl);
    cudaGetSymbolAddress((void**)&p_wvh, g_wvh);
    cudaGetSymbolAddress((void**)&p_wvl, g_wvl);
    cudaGetSymbolAddress((void**)&p_woh, g_woh);
    cudaGetSymbolAddress((void**)&p_wol, g_wol);
    cudaGetSymbolAddress((void**)&p_qh,  g_qh);
    cudaGetSymbolAddress((void**)&p_ql,  g_ql);
    cudaGetSymbolAddress((void**)&p_kh,  g_kh);
    cudaGetSymbolAddress((void**)&p_klo, g_klo);
    cudaGetSymbolAddress((void**)&p_vth, g_vth);
    cudaGetSymbolAddress((void**)&p_vtl, g_vtl);

    cudaFuncSetAttribute(tgemm_kernel, cudaFuncAttributeMaxDynamicSharedMemorySize, TG_SMEM);
    cudaFuncSetAttribute(flash_mma_kernel, cudaFuncAttributeMaxDynamicSharedMemorySize, FA2_SMEM);

    // 0) split conversions
    conv_split_kernel<<<(S_LEN * EMB / 4 + 255) / 256, 256>>>(hs, p_ah, p_al, S_LEN * EMB / 4);
    conv_split_t_kernel<<<dim3(EMB / 32, EMB / 32), dim3(32, 8)>>>(Wq, p_wqh, p_wql, EMB, EMB);
    conv_split_t_kernel<<<dim3(KVD / 32, EMB / 32), dim3(32, 8)>>>(Wk, p_wkh, p_wkl, EMB, KVD);
    conv_split_t_kernel<<<dim3(KVD / 32, EMB / 32), dim3(32, 8)>>>(Wv, p_wvh, p_wvl, EMB, KVD);
    conv_split_t_kernel<<<dim3(EMB / 32, EMB / 32), dim3(32, 8)>>>(Wo, p_woh, p_wol, EMB, EMB);

    // 1) projections (HMMA)
    tgemm_kernel<<<dim3(EMB / 128, S_LEN / 128), 256, TG_SMEM>>>(p_ah, p_al, p_wqh, p_wql, p_q, EMB, EMB);
    tgemm_kernel<<<dim3(KVD / 128, S_LEN / 128), 256, TG_SMEM>>>(p_ah, p_al, p_wkh, p_wkl, p_k, KVD, EMB);
    tgemm_kernel<<<dim3(KVD / 128, S_LEN / 128), 256, TG_SMEM>>>(p_ah, p_al, p_wvh, p_wvl, p_v, KVD, EMB);

    // 2) RoPE -> split-bf16 attention operands
    rope_table_kernel<<<S_LEN, 64>>>(pos);
    rope_split_kernel<<<dim3(S_LEN, NHEADS), 64>>>(p_q, p_qh, p_ql, EMB, 0.08838834764831845f);
    rope_split_kernel<<<dim3(S_LEN, NKVH),  64>>>(p_k, p_kh, p_klo, KVD, 1.0f);
    // V^T split: g_v [S,KVD] -> [KVD][S] = [kvh*128+d][s]
    conv_split_t_kernel<<<dim3(KVD / 32, S_LEN / 32), dim3(32, 8)>>>(p_v, p_vth, p_vtl, S_LEN, KVD);

    // 3) causal flash attention (HMMA)
    flash_mma_kernel<<<dim3(S_LEN / 64, NHEADS), 256, FA2_SMEM>>>();

    // 4) output projection (HMMA)
    conv_split_kernel<<<(S_LEN * EMB / 4 + 255) / 256, 256>>>(p_ao, p_aoh, p_aol, S_LEN * EMB / 4);
    tgemm_kernel<<<dim3(EMB / 128, S_LEN / 128), 256, TG_SMEM>>>(p_aoh, p_aol, p_woh, p_wol, out, EMB, EMB);
}

// round 10
// speedup vs baseline: 3.4119x; 1.0326x over previous
#include <cuda_runtime.h>
#include <cuda_bf16.h>
#include <math.h>
#include <stdint.h>

#define S_LEN 4096
#define EMB   2048
#define NHEADS 16
#define NKVH   4
#define HDv    128
#define KVD    (NKVH * HDv)   // 512

// ------------------- scratch (device globals; no allocations) -------------------
__device__ float g_q [S_LEN * EMB];
__device__ float g_k [S_LEN * KVD];
__device__ float g_v [S_LEN * KVD];
__device__ float g_ao[S_LEN * EMB];
__device__ float g_cos[S_LEN * 64];
__device__ float g_sin[S_LEN * 64];
// split-bf16 operands (GEMM)
__device__ __nv_bfloat16 g_ah [S_LEN * EMB], g_al [S_LEN * EMB];
__device__ __nv_bfloat16 g_aoh[S_LEN * EMB], g_aol[S_LEN * EMB];
__device__ __nv_bfloat16 g_wqh[EMB * EMB], g_wql[EMB * EMB];
__device__ __nv_bfloat16 g_wkh[KVD * EMB], g_wkl[KVD * EMB];
__device__ __nv_bfloat16 g_wvh[KVD * EMB], g_wvl[KVD * EMB];
__device__ __nv_bfloat16 g_woh[EMB * EMB], g_wol[EMB * EMB];
// split-bf16 attention operands
__device__ __nv_bfloat16 g_qh [NHEADS * S_LEN * HDv], g_ql [NHEADS * S_LEN * HDv]; // [h][s][d]
__device__ __nv_bfloat16 g_kh [NKVH * S_LEN * HDv],   g_klo[NKVH * S_LEN * HDv];   // [kvh][s][d]
__device__ __nv_bfloat16 g_vth[NKVH * HDv * S_LEN],   g_vtl[NKVH * HDv * S_LEN];   // [kvh][d][s]

// ------------------- helpers -------------------
__device__ __forceinline__ uint32_t smem_u32(const void* p) {
    uint32_t a;
    asm("{ .reg .u64 t; cvta.to.shared.u64 t, %1; cvt.u32.u64 %0, t; }" : "=r"(a) : "l"(p));
    return a;
}
#define SMEM_SWZ(off) ((off) ^ (((off) >> 3) & 0x70))

#define LDSM4(r, a) \
    asm volatile("ldmatrix.sync.aligned.m8n8.x4.shared.b16 {%0,%1,%2,%3}, [%4];" \
        : "=r"((r)[0]), "=r"((r)[1]), "=r"((r)[2]), "=r"((r)[3]) : "r"(a))

#define MMA16816(d, a, b0v, b1v) \
    asm volatile("mma.sync.aligned.m16n8k16.row.col.f32.bf16.bf16.f32 " \
        "{%0,%1,%2,%3}, {%4,%5,%6,%7}, {%8,%9}, {%0,%1,%2,%3};" \
        : "+f"((d)[0]), "+f"((d)[1]), "+f"((d)[2]), "+f"((d)[3]) \
        : "r"((a)[0]), "r"((a)[1]), "r"((a)[2]), "r"((a)[3]), "r"(b0v), "r"(b1v))

#define CP_ASYNC16(s, g) \
    asm volatile("cp.async.cg.shared.global [%0], [%1], 16;" :: "r"(s), "l"(g))
#define CP_COMMIT() asm volatile("cp.async.commit_group;" ::: "memory")
#define CP_WAIT1()  asm volatile("cp.async.wait_group 1;" ::: "memory")
#define CP_WAIT0()  asm volatile("cp.async.wait_group 0;" ::: "memory")

// split a,b into packed bf16x2 hi and lo (lower half = a, upper half = b)
__device__ __forceinline__ void split2(float a, float b, uint32_t& ph, uint32_t& pl) {
    float ha = __bfloat162float(__float2bfloat16(a));
    float hb = __bfloat162float(__float2bfloat16(b));
    asm("cvt.rn.bf16x2.f32 %0, %1, %2;" : "=r"(ph) : "f"(hb), "f"(ha));
    asm("cvt.rn.bf16x2.f32 %0, %1, %2;" : "=r"(pl) : "f"(b - hb), "f"(a - ha));
}

// ------------------- split conversion: fp32 -> (hi, lo) bf16 -------------------
__global__ __launch_bounds__(256) void conv_split_kernel(
    const float* __restrict__ src, __nv_bfloat16* __restrict__ hi,
    __nv_bfloat16* __restrict__ lo, int n4)
{
    int i = blockIdx.x * 256 + threadIdx.x;
    if (i >= n4) return;
    float4 v = ((const float4*)src)[i];
    __nv_bfloat16 h0 = __float2bfloat16(v.x), h1 = __float2bfloat16(v.y);
    __nv_bfloat16 h2 = __float2bfloat16(v.z), h3 = __float2bfloat16(v.w);
    __nv_bfloat16 l0 = __float2bfloat16(v.x - __bfloat162float(h0));
    __nv_bfloat16 l1 = __float2bfloat16(v.y - __bfloat162float(h1));
    __nv_bfloat16 l2 = __float2bfloat16(v.z - __bfloat162float(h2));
    __nv_bfloat16 l3 = __float2bfloat16(v.w - __bfloat162float(h3));
    ((__nv_bfloat162*)hi)[i * 2]     = __nv_bfloat162(h0, h1);
    ((__nv_bfloat162*)hi)[i * 2 + 1] = __nv_bfloat162(h2, h3);
    ((__nv_bfloat162*)lo)[i * 2]     = __nv_bfloat162(l0, l1);
    ((__nv_bfloat162*)lo)[i * 2 + 1] = __nv_bfloat162(l2, l3);
}

// transpose + split: src [R',C] fp32 -> hi/lo [C,R] bf16
__global__ __launch_bounds__(256) void conv_split_t_kernel(
    const float* __restrict__ src, __nv_bfloat16* __restrict__ hi,
    __nv_bfloat16* __restrict__ lo, int R, int C)
{
    __shared__ float T[32][33];
    const int x = threadIdx.x, y = threadIdx.y;     // block (32, 8)
    const int c0 = blockIdx.x * 32, r0 = blockIdx.y * 32;
#pragma unroll
    for (int i = 0; i < 4; i++)
        T[y + 8 * i][x] = src[(size_t)(r0 + y + 8 * i) * C + c0 + x];
    __syncthreads();
#pragma unroll
    for (int i = 0; i < 4; i++) {
        int r = y + 8 * i;
        float v = T[x][r];
        __nv_bfloat16 h = __float2bfloat16(v);
        __nv_bfloat16 l = __float2bfloat16(v - __bfloat162float(h));
        size_t o = (size_t)(c0 + r) * R + r0 + x;
        hi[o] = h; lo[o] = l;
    }
}

// ------------------- mma.sync split-bf16 GEMM (verified R7) -------------------
#define TG_SMEM (2 * 65536)

__global__ __launch_bounds__(256, 1)
void tgemm_kernel(const __nv_bfloat16* __restrict__ Ah, const __nv_bfloat16* __restrict__ Al,
                  const __nv_bfloat16* __restrict__ Bh, const __nv_bfloat16* __restrict__ Bl,
                  float* __restrict__ C, int N, int K)
{
    extern __shared__ char dsm[];
    const uint32_t sb = smem_u32(dsm);
    const int tid = threadIdx.x;
    const int wid = tid >> 5, lane = tid & 31;
    const int warp_m = wid >> 2, warp_n = wid & 3;
    const int row0 = blockIdx.y * 128;
    const int col0 = blockIdx.x * 128;

    const int crow = tid >> 3;
    const int cu = tid & 7;

    const int r16 = lane & 15;
    const int khB = (lane >> 4) * 16;
    const int a_row = warp_m * 64 + r16;
    const int b_row = warp_n * 32 + r16;

    float d[4][4][4];
#pragma unroll
    for (int mf = 0; mf < 4; mf++)
#pragma unroll
        for (int nf = 0; nf < 4; nf++)
#pragma unroll
            for (int j = 0; j < 4; j++) d[mf][nf][j] = 0.f;

    const int nch = K >> 6;

    {
        uint32_t s0 = sb;
#pragma unroll
        for (int t = 0; t < 4; t++) {
            int row = crow + t * 32;
            uint32_t so = SMEM_SWZ((uint32_t)(row * 128 + cu * 16));
            size_t ga = (size_t)(row0 + row) * K + cu * 8;
            size_t gb = (size_t)(col0 + row) * K + cu * 8;
            CP_ASYNC16(s0 + so,         (const char*)(Ah + ga));
            CP_ASYNC16(s0 + 16384 + so, (const char*)(Al + ga));
            CP_ASYNC16(s0 + 32768 + so, (const char*)(Bh + gb));
            CP_ASYNC16(s0 + 49152 + so, (const char*)(Bl + gb));
        }
        CP_COMMIT();
    }

    for (int c = 0; c < nch; c++) {
        if (c + 1 < nch) {
            uint32_t s1 = sb + ((c + 1) & 1) * 65536;
            const int ke = (c + 1) * 64;
#pragma unroll
            for (int t = 0; t < 4; t++) {
                int row = crow + t * 32;
                uint32_t so = SMEM_SWZ((uint32_t)(row * 128 + cu * 16));
                size_t ga = (size_t)(row0 + row) * K + ke + cu * 8;
                size_t gb = (size_t)(col0 + row) * K + ke + cu * 8;
                CP_ASYNC16(s1 + so,         (const char*)(Ah + ga));
                CP_ASYNC16(s1 + 16384 + so, (const char*)(Al + ga));
                CP_ASYNC16(s1 + 32768 + so, (const char*)(Bh + gb));
                CP_ASYNC16(s1 + 49152 + so, (const char*)(Bl + gb));
            }
            CP_COMMIT();
            CP_WAIT1();
        } else {
            CP_WAIT0();
        }
        __syncthreads();

        const uint32_t buf = sb + (c & 1) * 65536;
#pragma unroll
        for (int ks = 0; ks < 4; ks++) {
            uint32_t ah[4][4], al[4][4], bh[2][4], bl[2][4];
#pragma unroll
            for (int mf = 0; mf < 4; mf++) {
                uint32_t off = SMEM_SWZ((uint32_t)((a_row + mf * 16) * 128 + ks * 32 + khB));
                LDSM4(ah[mf], buf + off);
                LDSM4(al[mf], buf + 16384 + off);
            }
#pragma unroll
            for (int np = 0; np < 2; np++) {
                uint32_t off = SMEM_SWZ((uint32_t)((b_row + np * 16) * 128 + ks * 32 + khB));
                LDSM4(bh[np], buf + 32768 + off);
                LDSM4(bl[np], buf + 49152 + off);
            }
#pragma unroll
            for (int mf = 0; mf < 4; mf++)
#pragma unroll
                for (int nf = 0; nf < 4; nf++) {
                    const int np = nf >> 1, h = nf & 1;
                    MMA16816(d[mf][nf], ah[mf], bh[np][h], bh[np][2 + h]);
                    MMA16816(d[mf][nf], ah[mf], bl[np][h], bl[np][2 + h]);
                    MMA16816(d[mf][nf], al[mf], bh[np][h], bh[np][2 + h]);
                }
        }
        __syncthreads();
    }

    const int g = lane >> 2, tig = lane & 3;
#pragma unroll
    for (int mf = 0; mf < 4; mf++)
#pragma unroll
        for (int nf = 0; nf < 4; nf++) {
            int row = row0 + warp_m * 64 + mf * 16 + g;
            int col = col0 + warp_n * 32 + nf * 8 + tig * 2;
            *(float2*)&C[(size_t)row * N + col] = make_float2(d[mf][nf][0], d[mf][nf][1]);
            *(float2*)&C[(size_t)(row + 8) * N + col] = make_float2(d[mf][nf][2], d[mf][nf][3]);
        }
}

// ------------------- RoPE table (fp64 sincos once per (s,d)) -------------------
__global__ void rope_table_kernel(const int* __restrict__ pos_ids) {
    int s = blockIdx.x, d = threadIdx.x;
    double inv = pow(1000000.0, -(double)d / 64.0);
    double ang = (double)pos_ids[s] * inv;
    double sd, cd; sincos(ang, &sd, &cd);
    g_cos[s * 64 + d] = (float)cd;
    g_sin[s * 64 + d] = (float)sd;
}

// ------------------- RoPE apply + split to bf16 hi/lo [h][s][d] -------------------
__global__ void rope_split_kernel(const float* __restrict__ src,
                                  __nv_bfloat16* __restrict__ oh,
                                  __nv_bfloat16* __restrict__ ol,
                                  int ncols, float sc)
{
    int s = blockIdx.x, h = blockIdx.y, d = threadIdx.x;  // d in [0,64)
    float c  = g_cos[s * 64 + d];
    float sn = g_sin[s * 64 + d];
    const float* p = src + (size_t)s * ncols + h * HDv;
    float x0 = p[d], x1 = p[d + 64];
    float y0 = (x0 * c - x1 * sn) * sc;
    float y1 = (x1 * c + x0 * sn) * sc;
    size_t o = ((size_t)h * S_LEN + s) * HDv + d;
    __nv_bfloat16 h0 = __float2bfloat16(y0);
    __nv_bfloat16 h1 = __float2bfloat16(y1);
    oh[o] = h0;      ol[o]      = __float2bfloat16(y0 - __bfloat162float(h0));
    oh[o + 64] = h1; ol[o + 64] = __float2bfloat16(y1 - __bfloat162float(h1));
}

// ------------------- Flash attention: mma.sync split-bf16, BM=128 -------------------
// CTA: 128 q-rows x one head; 8 warps, warp wm owns q-rows wm*16..wm*16+15 and
// the FULL 64-kv block => softmax is warp-local (quad shuffles only).
// smem: Qh [0,34816) Ql [34816,69632) pitch 272;
//       K bufs at 69632: 2 x [Kh 17408 | Kl 17408] pitch 272;
//       V bufs at 139264: 2 x [Vh 18432 | Vl 18432] pitch 144 (rows=d, cols=s).
#define FQOFF   0
#define FQLOFF  34816
#define FKOFF   69632
#define FVOFF   139264
#define FA2_SMEM 212992

__global__ __launch_bounds__(256, 1) void flash_mma_kernel() {
    extern __shared__ char fsm[];
    const uint32_t sb = smem_u32(fsm);
    const int tid = threadIdx.x;
    const int wm = tid >> 5, lane = tid & 31;
    const int g = lane >> 2, tig = lane & 3;
    const int r16 = lane & 15;
    const int khB = (lane >> 4) * 16;
    const int h = blockIdx.y;
    const int qb = (int)gridDim.x - 1 - (int)blockIdx.x;  // long CTAs first
    const int q0 = qb * 128;
    const int kvh = h >> 2;

    const char* qhp = (const char*)(g_qh  + ((size_t)h * S_LEN + q0) * HDv);
    const char* qlp = (const char*)(g_ql  + ((size_t)h * S_LEN + q0) * HDv);
    const char* khp = (const char*)(g_kh  + (size_t)kvh * S_LEN * HDv);
    const char* klp = (const char*)(g_klo + (size_t)kvh * S_LEN * HDv);
    const char* vhp = (const char*)(g_vth + (size_t)kvh * HDv * S_LEN);
    const char* vlp = (const char*)(g_vtl + (size_t)kvh * HDv * S_LEN);

    // Q tile (128 x 128 bf16 hi/lo)
#pragma unroll
    for (int t = 0; t < 8; t++) {
        int idx = tid + t * 256;
        int row = idx >> 4, u = idx & 15;
        CP_ASYNC16(sb + FQOFF  + row * 272 + u * 16, qhp + row * 256 + u * 16);
        CP_ASYNC16(sb + FQLOFF + row * 272 + u * 16, qlp + row * 256 + u * 16);
    }
    // KV block 0
#pragma unroll
    for (int t = 0; t < 4; t++) {
        int idx = tid + t * 256;
        int row = idx >> 4, u = idx & 15;
        CP_ASYNC16(sb + FKOFF + row * 272 + u * 16,         khp + row * 256 + u * 16);
        CP_ASYNC16(sb + FKOFF + 17408 + row * 272 + u * 16, klp + row * 256 + u * 16);
        int vr = idx >> 3, vu = idx & 7;
        CP_ASYNC16(sb + FVOFF + vr * 144 + vu * 16,         vhp + (size_t)vr * (S_LEN * 2) + vu * 16);
        CP_ASYNC16(sb + FVOFF + 18432 + vr * 144 + vu * 16, vlp + (size_t)vr * (S_LEN * 2) + vu * 16);
    }
    CP_COMMIT();

    float m_run[2] = {-1e30f, -1e30f};
    float l_run[2] = {0.f, 0.f};
    float o[16][4];
#pragma unroll
    for (int i = 0; i < 16; i++) { o[i][0] = o[i][1] = o[i][2] = o[i][3] = 0.f; }

    const int nkb = 2 * qb + 2;

    for (int kb = 0; kb < nkb; kb++) {
        if (kb + 1 < nkb) {
            const size_t k0n = (size_t)(kb + 1) * 64;
            uint32_t KB = sb + FKOFF + ((kb + 1) & 1) * 34816;
            uint32_t VB = sb + FVOFF + ((kb + 1) & 1) * 36864;
#pragma unroll
            for (int t = 0; t < 4; t++) {
                int idx = tid + t * 256;
                int row = idx >> 4, u = idx & 15;
                CP_ASYNC16(KB + row * 272 + u * 16,         khp + (k0n + row) * 256 + u * 16);
                CP_ASYNC16(KB + 17408 + row * 272 + u * 16, klp + (k0n + row) * 256 + u * 16);
                int vr = idx >> 3, vu = idx & 7;
                CP_ASYNC16(VB + vr * 144 + vu * 16,         vhp + (size_t)vr * (S_LEN * 2) + k0n * 2 + vu * 16);
                CP_ASYNC16(VB + 18432 + vr * 144 + vu * 16, vlp + (size_t)vr * (S_LEN * 2) + k0n * 2 + vu * 16);
            }
            CP_COMMIT();
            CP_WAIT1();
        } else {
            CP_WAIT0();
        }
        __syncthreads();

        const int k0 = kb * 64;
        // warp-skip: this warp's rows are q0+wm*16 .. +15; block fully masked if k0 > max row
        if (k0 <= q0 + wm * 16 + 15) {
            const uint32_t KB = sb + FKOFF + (kb & 1) * 34816;
            const uint32_t VB = sb + FVOFF + (kb & 1) * 36864;

            // ---- S = Q K^T (split 3-pass): s[8][4] covers 16 rows x 64 kv ----
            float s[8][4];
#pragma unroll
            for (int nf = 0; nf < 8; nf++) s[nf][0] = s[nf][1] = s[nf][2] = s[nf][3] = 0.f;
#pragma unroll
            for (int ks = 0; ks < 8; ks++) {
                uint32_t aqh[4], aql[4], bkh[4][4], bkl[4][4];
                uint32_t qo = (uint32_t)((wm * 16 + r16) * 272 + ks * 32 + khB);
                LDSM4(aqh, sb + FQOFF + qo);
                LDSM4(aql, sb + FQLOFF + qo);
#pragma unroll
                for (int np = 0; np < 4; np++) {
                    uint32_t ko = (uint32_t)((np * 16 + r16) * 272 + ks * 32 + khB);
                    LDSM4(bkh[np], KB + ko);
                    LDSM4(bkl[np], KB + 17408 + ko);
                }
#pragma unroll
                for (int nf = 0; nf < 8; nf++) {
                    const int np = nf >> 1, hs = nf & 1;
                    MMA16816(s[nf], aqh, bkh[np][hs], bkh[np][2 + hs]);
                    MMA16816(s[nf], aqh, bkl[np][hs], bkl[np][2 + hs]);
                    MMA16816(s[nf], aql, bkh[np][hs], bkh[np][2 + hs]);
                }
            }

            if (kb >= 2 * qb) {  // blocks overlapping the diagonal
#pragma unroll
                for (int nf = 0; nf < 8; nf++)
#pragma unroll
                    for (int j = 0; j < 4; j++) {
                        int r = q0 + wm * 16 + g + ((j >> 1) << 3);
                        int c = k0 + nf * 8 + tig * 2 + (j & 1);
                        if (c > r) s[nf][j] = -1e30f;
                    }
            }

            // ---- warp-local online softmax (quad shuffles only) ----
            float rmx0 = -1e30f, rmx1 = -1e30f;
#pragma unroll
            for (int nf = 0; nf < 8; nf++) {
                rmx0 = fmaxf(rmx0, fmaxf(s[nf][0], s[nf][1]));
                rmx1 = fmaxf(rmx1, fmaxf(s[nf][2], s[nf][3]));
            }
            rmx0 = fmaxf(rmx0, __shfl_xor_sync(0xffffffffu, rmx0, 1));
            rmx0 = fmaxf(rmx0, __shfl_xor_sync(0xffffffffu, rmx0, 2));
            rmx1 = fmaxf(rmx1, __shfl_xor_sync(0xffffffffu, rmx1, 1));
            rmx1 = fmaxf(rmx1, __shfl_xor_sync(0xffffffffu, rmx1, 2));
            float mn0 = fmaxf(m_run[0], rmx0);
            float mn1 = fmaxf(m_run[1], rmx1);
            float fs0 = __expf(m_run[0] - mn0);
            float fs1 = __expf(m_run[1] - mn1);
            m_run[0] = mn0; m_run[1] = mn1;

            float sum0 = 0.f, sum1 = 0.f;
#pragma unroll
            for (int nf = 0; nf < 8; nf++) {
                s[nf][0] = __expf(s[nf][0] - mn0);
                s[nf][1] = __expf(s[nf][1] - mn0);
                s[nf][2] = __expf(s[nf][2] - mn1);
                s[nf][3] = __expf(s[nf][3] - mn1);
                sum0 += s[nf][0] + s[nf][1];
                sum1 += s[nf][2] + s[nf][3];
            }
            sum0 += __shfl_xor_sync(0xffffffffu, sum0, 1);
            sum0 += __shfl_xor_sync(0xffffffffu, sum0, 2);
            sum1 += __shfl_xor_sync(0xffffffffu, sum1, 1);
            sum1 += __shfl_xor_sync(0xffffffffu, sum1, 2);
            l_run[0] = l_run[0] * fs0 + sum0;
            l_run[1] = l_run[1] * fs1 + sum1;

#pragma unroll
            for (int i = 0; i < 16; i++) {
                o[i][0] *= fs0; o[i][1] *= fs0; o[i][2] *= fs1; o[i][3] *= fs1;
            }

            // ---- P A-frags (register reuse, split hi/lo): 4 k-steps of 16 kv ----
            uint32_t aph[4][4], apl[4][4];
#pragma unroll
            for (int kk = 0; kk < 4; kk++) {
                const int nfA = 2 * kk, nfB = 2 * kk + 1;
                split2(s[nfA][0], s[nfA][1], aph[kk][0], apl[kk][0]);
                split2(s[nfA][2], s[nfA][3], aph[kk][1], apl[kk][1]);
                split2(s[nfB][0], s[nfB][1], aph[kk][2], apl[kk][2]);
                split2(s[nfB][2], s[nfB][3], aph[kk][3], apl[kk][3]);
            }

            // ---- O += P V (split 3-pass) over full 64 kv ----
#pragma unroll
            for (int kk = 0; kk < 4; kk++) {
#pragma unroll
                for (int np = 0; np < 8; np++) {
                    uint32_t bvh[4], bvl[4];
                    uint32_t vo = (uint32_t)((np * 16 + r16) * 144 + kk * 32 + khB);
                    LDSM4(bvh, VB + vo);
                    LDSM4(bvl, VB + 18432 + vo);
#pragma unroll
                    for (int hs = 0; hs < 2; hs++) {
                        const int nd = np * 2 + hs;
                        MMA16816(o[nd], aph[kk], bvh[hs], bvh[2 + hs]);
                        MMA16816(o[nd], aph[kk], bvl[hs], bvl[2 + hs]);
                        MMA16816(o[nd], apl[kk], bvh[hs], bvh[2 + hs]);
                    }
                }
            }
        }
        __syncthreads();   // protect smem buffers before next fill
    }

    // ---- epilogue: normalize, store directly ----
    float inv0 = 1.f / l_run[0], inv1 = 1.f / l_run[1];
    float* d0 = g_ao + (size_t)(q0 + wm * 16 + g) * EMB + h * HDv;
    float* d1 = g_ao + (size_t)(q0 + wm * 16 + g + 8) * EMB + h * HDv;
#pragma unroll
    for (int nd = 0; nd < 16; nd++) {
        int c = nd * 8 + tig * 2;
        *(float2*)(d0 + c) = make_float2(o[nd][0] * inv0, o[nd][1] * inv0);
        *(float2*)(d1 + c) = make_float2(o[nd][2] * inv1, o[nd][3] * inv1);
    }
}

// ------------------- launch -------------------
extern "C" void kernel_launch(void* const* d_in, const int* in_sizes, int n_in,
                              void* d_out, int out_size)
{
    const float* hs = (const float*)d_in[0];
    const float* Wq = (const float*)d_in[1];
    const float* Wk = (const float*)d_in[2];
    const float* Wv = (const float*)d_in[3];
    const float* Wo = (const float*)d_in[4];
    const int*   pos = (const int*)d_in[6];
    float* out = (float*)d_out;

    float *p_q, *p_k, *p_v, *p_ao;
    cudaGetSymbolAddress((void**)&p_q,  g_q);
    cudaGetSymbolAddress((void**)&p_k,  g_k);
    cudaGetSymbolAddress((void**)&p_v,  g_v);
    cudaGetSymbolAddress((void**)&p_ao, g_ao);
    __nv_bfloat16 *p_ah, *p_al, *p_aoh, *p_aol;
    __nv_bfloat16 *p_wqh, *p_wql, *p_wkh, *p_wkl, *p_wvh, *p_wvl, *p_woh, *p_wol;
    __nv_bfloat16 *p_qh, *p_ql, *p_kh, *p_klo, *p_vth, *p_vtl;
    cudaGetSymbolAddress((void**)&p_ah,  g_ah);
    cudaGetSymbolAddress((void**)&p_al,  g_al);
    cudaGetSymbolAddress((void**)&p_aoh, g_aoh);
    cudaGetSymbolAddress((void**)&p_aol, g_aol);
    cudaGetSymbolAddress((void**)&p_wqh, g_wqh);
    cudaGetSymbolAddress((void**)&p_wql, g_wql);
    cudaGetSymbolAddress((void**)&p_wkh, g_wkh);
    cudaGetSymbolAddress((void**)&p_wkl, g_wkl);
    cudaGetSymbolAddress((void**)&p_wvh, g_wvh);
    cudaGetSymbolAddress((void**)&p_wvl, g_wvl);
    cudaGetSymbolAddress((void**)&p_woh, g_woh);
    cudaGetSymbolAddress((void**)&p_wol, g_wol);
    cudaGetSymbolAddress((void**)&p_qh,  g_qh);
    cudaGetSymbolAddress((void**)&p_ql,  g_ql);
    cudaGetSymbolAddress((void**)&p_kh,  g_kh);
    cudaGetSymbolAddress((void**)&p_klo, g_klo);
    cudaGetSymbolAddress((void**)&p_vth, g_vth);
    cudaGetSymbolAddress((void**)&p_vtl, g_vtl);

    cudaFuncSetAttribute(tgemm_kernel, cudaFuncAttributeMaxDynamicSharedMemorySize, TG_SMEM);
    cudaFuncSetAttribute(flash_mma_kernel, cudaFuncAttributeMaxDynamicSharedMemorySize, FA2_SMEM);

    // 0) split conversions
    conv_split_kernel<<<(S_LEN * EMB / 4 + 255) / 256, 256>>>(hs, p_ah, p_al, S_LEN * EMB / 4);
    conv_split_t_kernel<<<dim3(EMB / 32, EMB / 32), dim3(32, 8)>>>(Wq, p_wqh, p_wql, EMB, EMB);
    conv_split_t_kernel<<<dim3(KVD / 32, EMB / 32), dim3(32, 8)>>>(Wk, p_wkh, p_wkl, EMB, KVD);
    conv_split_t_kernel<<<dim3(KVD / 32, EMB / 32), dim3(32, 8)>>>(Wv, p_wvh, p_wvl, EMB, KVD);
    conv_split_t_kernel<<<dim3(EMB / 32, EMB / 32), dim3(32, 8)>>>(Wo, p_woh, p_wol, EMB, EMB);

    // 1) projections (HMMA)
    tgemm_kernel<<<dim3(EMB / 128, S_LEN / 128), 256, TG_SMEM>>>(p_ah, p_al, p_wqh, p_wql, p_q, EMB, EMB);
    tgemm_kernel<<<dim3(KVD / 128, S_LEN / 128), 256, TG_SMEM>>>(p_ah, p_al, p_wkh, p_wkl, p_k, KVD, EMB);
    tgemm_kernel<<<dim3(KVD / 128, S_LEN / 128), 256, TG_SMEM>>>(p_ah, p_al, p_wvh, p_wvl, p_v, KVD, EMB);

    // 2) RoPE -> split-bf16 attention operands
    rope_table_kernel<<<S_LEN, 64>>>(pos);
    rope_split_kernel<<<dim3(S_LEN, NHEADS), 64>>>(p_q, p_qh, p_ql, EMB, 0.08838834764831845f);
    rope_split_kernel<<<dim3(S_LEN, NKVH),  64>>>(p_k, p_kh, p_klo, KVD, 1.0f);
    conv_split_t_kernel<<<dim3(KVD / 32, S_LEN / 32), dim3(32, 8)>>>(p_v, p_vth, p_vtl, S_LEN, KVD);

    // 3) causal flash attention (HMMA, BM=128)
    flash_mma_kernel<<<dim3(S_LEN / 128, NHEADS), 256, FA2_SMEM>>>();

    // 4) output projection (HMMA)
    conv_split_kernel<<<(S_LEN * EMB / 4 + 255) / 256, 256>>>(p_ao, p_aoh, p_aol, S_LEN * EMB / 4);
    tgemm_kernel<<<dim3(EMB / 128, S_LEN / 128), 256, TG_SMEM>>>(p_aoh, p_aol, p_woh, p_wol, out, EMB, EMB);
}

// round 11
// speedup vs baseline: 3.8780x; 1.1366x over previous
#include <cuda_runtime.h>
#include <cuda_bf16.h>
#include <math.h>
#include <stdint.h>

#define S_LEN 4096
#define EMB   2048
#define NHEADS 16
#define NKVH   4
#define HDv    128
#define KVD    (NKVH * HDv)   // 512

// ------------------- scratch (device globals; no allocations) -------------------
__device__ float g_q [S_LEN * EMB];
__device__ float g_k [S_LEN * KVD];
__device__ float g_v [S_LEN * KVD];
__device__ float g_ao[S_LEN * EMB];
__device__ float g_cos[S_LEN * 64];
__device__ float g_sin[S_LEN * 64];
// split-bf16 operands (GEMM)
__device__ __nv_bfloat16 g_ah [S_LEN * EMB], g_al [S_LEN * EMB];
__device__ __nv_bfloat16 g_aoh[S_LEN * EMB], g_aol[S_LEN * EMB];
__device__ __nv_bfloat16 g_wqh[EMB * EMB], g_wql[EMB * EMB];
__device__ __nv_bfloat16 g_wkh[KVD * EMB], g_wkl[KVD * EMB];
__device__ __nv_bfloat16 g_wvh[KVD * EMB], g_wvl[KVD * EMB];
__device__ __nv_bfloat16 g_woh[EMB * EMB], g_wol[EMB * EMB];
// attention operands: Q/K hi-only (abs S error ~1e-6, negligible); V split hi/lo
__device__ __nv_bfloat16 g_qh [NHEADS * S_LEN * HDv];                            // [h][s][d]
__device__ __nv_bfloat16 g_kh [NKVH * S_LEN * HDv];                              // [kvh][s][d]
__device__ __nv_bfloat16 g_vth[NKVH * HDv * S_LEN], g_vtl[NKVH * HDv * S_LEN];   // [kvh][d][s]

// ------------------- helpers -------------------
__device__ __forceinline__ uint32_t smem_u32(const void* p) {
    uint32_t a;
    asm("{ .reg .u64 t; cvta.to.shared.u64 t, %1; cvt.u32.u64 %0, t; }" : "=r"(a) : "l"(p));
    return a;
}
#define SMEM_SWZ(off) ((off) ^ (((off) >> 3) & 0x70))

#define LDSM4(r, a) \
    asm volatile("ldmatrix.sync.aligned.m8n8.x4.shared.b16 {%0,%1,%2,%3}, [%4];" \
        : "=r"((r)[0]), "=r"((r)[1]), "=r"((r)[2]), "=r"((r)[3]) : "r"(a))

#define MMA16816(d, a, b0v, b1v) \
    asm volatile("mma.sync.aligned.m16n8k16.row.col.f32.bf16.bf16.f32 " \
        "{%0,%1,%2,%3}, {%4,%5,%6,%7}, {%8,%9}, {%0,%1,%2,%3};" \
        : "+f"((d)[0]), "+f"((d)[1]), "+f"((d)[2]), "+f"((d)[3]) \
        : "r"((a)[0]), "r"((a)[1]), "r"((a)[2]), "r"((a)[3]), "r"(b0v), "r"(b1v))

#define CP_ASYNC16(s, g) \
    asm volatile("cp.async.cg.shared.global [%0], [%1], 16;" :: "r"(s), "l"(g))
#define CP_COMMIT() asm volatile("cp.async.commit_group;" ::: "memory")
#define CP_WAIT1()  asm volatile("cp.async.wait_group 1;" ::: "memory")
#define CP_WAIT0()  asm volatile("cp.async.wait_group 0;" ::: "memory")

// split a,b into packed bf16x2 hi and lo (lower half = a, upper half = b)
__device__ __forceinline__ void split2(float a, float b, uint32_t& ph, uint32_t& pl) {
    float ha = __bfloat162float(__float2bfloat16(a));
    float hb = __bfloat162float(__float2bfloat16(b));
    asm("cvt.rn.bf16x2.f32 %0, %1, %2;" : "=r"(ph) : "f"(hb), "f"(ha));
    asm("cvt.rn.bf16x2.f32 %0, %1, %2;" : "=r"(pl) : "f"(b - hb), "f"(a - ha));
}

// ------------------- split conversion: fp32 -> (hi, lo) bf16 -------------------
__global__ __launch_bounds__(256) void conv_split_kernel(
    const float* __restrict__ src, __nv_bfloat16* __restrict__ hi,
    __nv_bfloat16* __restrict__ lo, int n4)
{
    int i = blockIdx.x * 256 + threadIdx.x;
    if (i >= n4) return;
    float4 v = ((const float4*)src)[i];
    __nv_bfloat16 h0 = __float2bfloat16(v.x), h1 = __float2bfloat16(v.y);
    __nv_bfloat16 h2 = __float2bfloat16(v.z), h3 = __float2bfloat16(v.w);
    __nv_bfloat16 l0 = __float2bfloat16(v.x - __bfloat162float(h0));
    __nv_bfloat16 l1 = __float2bfloat16(v.y - __bfloat162float(h1));
    __nv_bfloat16 l2 = __float2bfloat16(v.z - __bfloat162float(h2));
    __nv_bfloat16 l3 = __float2bfloat16(v.w - __bfloat162float(h3));
    ((__nv_bfloat162*)hi)[i * 2]     = __nv_bfloat162(h0, h1);
    ((__nv_bfloat162*)hi)[i * 2 + 1] = __nv_bfloat162(h2, h3);
    ((__nv_bfloat162*)lo)[i * 2]     = __nv_bfloat162(l0, l1);
    ((__nv_bfloat162*)lo)[i * 2 + 1] = __nv_bfloat162(l2, l3);
}

// transpose + split: src [R',C] fp32 -> hi/lo [C,R] bf16
__global__ __launch_bounds__(256) void conv_split_t_kernel(
    const float* __restrict__ src, __nv_bfloat16* __restrict__ hi,
    __nv_bfloat16* __restrict__ lo, int R, int C)
{
    __shared__ float T[32][33];
    const int x = threadIdx.x, y = threadIdx.y;     // block (32, 8)
    const int c0 = blockIdx.x * 32, r0 = blockIdx.y * 32;
#pragma unroll
    for (int i = 0; i < 4; i++)
        T[y + 8 * i][x] = src[(size_t)(r0 + y + 8 * i) * C + c0 + x];
    __syncthreads();
#pragma unroll
    for (int i = 0; i < 4; i++) {
        int r = y + 8 * i;
        float v = T[x][r];
        __nv_bfloat16 h = __float2bfloat16(v);
        __nv_bfloat16 l = __float2bfloat16(v - __bfloat162float(h));
        size_t o = (size_t)(c0 + r) * R + r0 + x;
        hi[o] = h; lo[o] = l;
    }
}

// ------------------- mma.sync split-bf16 GEMM (verified R7) -------------------
#define TG_SMEM (2 * 65536)

__global__ __launch_bounds__(256, 1)
void tgemm_kernel(const __nv_bfloat16* __restrict__ Ah, const __nv_bfloat16* __restrict__ Al,
                  const __nv_bfloat16* __restrict__ Bh, const __nv_bfloat16* __restrict__ Bl,
                  float* __restrict__ C, int N, int K)
{
    extern __shared__ char dsm[];
    const uint32_t sb = smem_u32(dsm);
    const int tid = threadIdx.x;
    const int wid = tid >> 5, lane = tid & 31;
    const int warp_m = wid >> 2, warp_n = wid & 3;
    const int row0 = blockIdx.y * 128;
    const int col0 = blockIdx.x * 128;

    const int crow = tid >> 3;
    const int cu = tid & 7;

    const int r16 = lane & 15;
    const int khB = (lane >> 4) * 16;
    const int a_row = warp_m * 64 + r16;
    const int b_row = warp_n * 32 + r16;

    float d[4][4][4];
#pragma unroll
    for (int mf = 0; mf < 4; mf++)
#pragma unroll
        for (int nf = 0; nf < 4; nf++)
#pragma unroll
            for (int j = 0; j < 4; j++) d[mf][nf][j] = 0.f;

    const int nch = K >> 6;

    {
        uint32_t s0 = sb;
#pragma unroll
        for (int t = 0; t < 4; t++) {
            int row = crow + t * 32;
            uint32_t so = SMEM_SWZ((uint32_t)(row * 128 + cu * 16));
            size_t ga = (size_t)(row0 + row) * K + cu * 8;
            size_t gb = (size_t)(col0 + row) * K + cu * 8;
            CP_ASYNC16(s0 + so,         (const char*)(Ah + ga));
            CP_ASYNC16(s0 + 16384 + so, (const char*)(Al + ga));
            CP_ASYNC16(s0 + 32768 + so, (const char*)(Bh + gb));
            CP_ASYNC16(s0 + 49152 + so, (const char*)(Bl + gb));
        }
        CP_COMMIT();
    }

    for (int c = 0; c < nch; c++) {
        if (c + 1 < nch) {
            uint32_t s1 = sb + ((c + 1) & 1) * 65536;
            const int ke = (c + 1) * 64;
#pragma unroll
            for (int t = 0; t < 4; t++) {
                int row = crow + t * 32;
                uint32_t so = SMEM_SWZ((uint32_t)(row * 128 + cu * 16));
                size_t ga = (size_t)(row0 + row) * K + ke + cu * 8;
                size_t gb = (size_t)(col0 + row) * K + ke + cu * 8;
                CP_ASYNC16(s1 + so,         (const char*)(Ah + ga));
                CP_ASYNC16(s1 + 16384 + so, (const char*)(Al + ga));
                CP_ASYNC16(s1 + 32768 + so, (const char*)(Bh + gb));
                CP_ASYNC16(s1 + 49152 + so, (const char*)(Bl + gb));
            }
            CP_COMMIT();
            CP_WAIT1();
        } else {
            CP_WAIT0();
        }
        __syncthreads();

        const uint32_t buf = sb + (c & 1) * 65536;
#pragma unroll
        for (int ks = 0; ks < 4; ks++) {
            uint32_t ah[4][4], al[4][4], bh[2][4], bl[2][4];
#pragma unroll
            for (int mf = 0; mf < 4; mf++) {
                uint32_t off = SMEM_SWZ((uint32_t)((a_row + mf * 16) * 128 + ks * 32 + khB));
                LDSM4(ah[mf], buf + off);
                LDSM4(al[mf], buf + 16384 + off);
            }
#pragma unroll
            for (int np = 0; np < 2; np++) {
                uint32_t off = SMEM_SWZ((uint32_t)((b_row + np * 16) * 128 + ks * 32 + khB));
                LDSM4(bh[np], buf + 32768 + off);
                LDSM4(bl[np], buf + 49152 + off);
            }
#pragma unroll
            for (int mf = 0; mf < 4; mf++)
#pragma unroll
                for (int nf = 0; nf < 4; nf++) {
                    const int np = nf >> 1, h = nf & 1;
                    MMA16816(d[mf][nf], ah[mf], bh[np][h], bh[np][2 + h]);
                    MMA16816(d[mf][nf], ah[mf], bl[np][h], bl[np][2 + h]);
                    MMA16816(d[mf][nf], al[mf], bh[np][h], bh[np][2 + h]);
                }
        }
        __syncthreads();
    }

    const int g = lane >> 2, tig = lane & 3;
#pragma unroll
    for (int mf = 0; mf < 4; mf++)
#pragma unroll
        for (int nf = 0; nf < 4; nf++) {
            int row = row0 + warp_m * 64 + mf * 16 + g;
            int col = col0 + warp_n * 32 + nf * 8 + tig * 2;
            *(float2*)&C[(size_t)row * N + col] = make_float2(d[mf][nf][0], d[mf][nf][1]);
            *(float2*)&C[(size_t)(row + 8) * N + col] = make_float2(d[mf][nf][2], d[mf][nf][3]);
        }
}

// ------------------- RoPE table (fp64 sincos once per (s,d)) -------------------
__global__ void rope_table_kernel(const int* __restrict__ pos_ids) {
    int s = blockIdx.x, d = threadIdx.x;
    double inv = pow(1000000.0, -(double)d / 64.0);
    double ang = (double)pos_ids[s] * inv;
    double sd, cd; sincos(ang, &sd, &cd);
    g_cos[s * 64 + d] = (float)cd;
    g_sin[s * 64 + d] = (float)sd;
}

// ------------------- RoPE apply -> bf16 (hi only) [h][s][d] -------------------
__global__ void rope_bf16_kernel(const float* __restrict__ src,
                                 __nv_bfloat16* __restrict__ oh,
                                 int ncols, float sc)
{
    int s = blockIdx.x, h = blockIdx.y, d = threadIdx.x;  // d in [0,64)
    float c  = g_cos[s * 64 + d];
    float sn = g_sin[s * 64 + d];
    const float* p = src + (size_t)s * ncols + h * HDv;
    float x0 = p[d], x1 = p[d + 64];
    size_t o = ((size_t)h * S_LEN + s) * HDv + d;
    oh[o]      = __float2bfloat16((x0 * c - x1 * sn) * sc);
    oh[o + 64] = __float2bfloat16((x1 * c + x0 * sn) * sc);
}

// ------------------- Flash attention: mma.sync, BM=128 -------------------
// Q/K hi-only (bf16), V split hi/lo. 8 warps; warp wm owns q-rows wm*16..+15
// and the full 64-kv block (warp-local softmax).
// smem: Qh [0,34816) pitch 272;
//       K bufs at 34816: 2 x [Kh 17408] pitch 272;
//       V bufs at 69632: 2 x [Vh 18432 | Vl 18432] pitch 144 (rows=d, cols=s).
#define FQOFF   0
#define FKOFF   34816
#define FVOFF   69632
#define FA2_SMEM 143360

__global__ __launch_bounds__(256, 1) void flash_mma_kernel() {
    extern __shared__ char fsm[];
    const uint32_t sb = smem_u32(fsm);
    const int tid = threadIdx.x;
    const int wm = tid >> 5, lane = tid & 31;
    const int g = lane >> 2, tig = lane & 3;
    const int r16 = lane & 15;
    const int khB = (lane >> 4) * 16;
    const int h = blockIdx.y;
    const int qb = (int)gridDim.x - 1 - (int)blockIdx.x;  // long CTAs first
    const int q0 = qb * 128;
    const int kvh = h >> 2;

    const char* qhp = (const char*)(g_qh  + ((size_t)h * S_LEN + q0) * HDv);
    const char* khp = (const char*)(g_kh  + (size_t)kvh * S_LEN * HDv);
    const char* vhp = (const char*)(g_vth + (size_t)kvh * HDv * S_LEN);
    const char* vlp = (const char*)(g_vtl + (size_t)kvh * HDv * S_LEN);

    // Q tile (128 x 128 bf16, hi only)
#pragma unroll
    for (int t = 0; t < 8; t++) {
        int idx = tid + t * 256;
        int row = idx >> 4, u = idx & 15;
        CP_ASYNC16(sb + FQOFF + row * 272 + u * 16, qhp + row * 256 + u * 16);
    }
    // KV block 0
#pragma unroll
    for (int t = 0; t < 4; t++) {
        int idx = tid + t * 256;
        int row = idx >> 4, u = idx & 15;
        CP_ASYNC16(sb + FKOFF + row * 272 + u * 16, khp + row * 256 + u * 16);
        int vr = idx >> 3, vu = idx & 7;
        CP_ASYNC16(sb + FVOFF + vr * 144 + vu * 16,         vhp + (size_t)vr * (S_LEN * 2) + vu * 16);
        CP_ASYNC16(sb + FVOFF + 18432 + vr * 144 + vu * 16, vlp + (size_t)vr * (S_LEN * 2) + vu * 16);
    }
    CP_COMMIT();

    float m_run[2] = {-1e30f, -1e30f};
    float l_run[2] = {0.f, 0.f};
    float o[16][4];
#pragma unroll
    for (int i = 0; i < 16; i++) { o[i][0] = o[i][1] = o[i][2] = o[i][3] = 0.f; }

    const int nkb = 2 * qb + 2;

    for (int kb = 0; kb < nkb; kb++) {
        if (kb + 1 < nkb) {
            const size_t k0n = (size_t)(kb + 1) * 64;
            uint32_t KB = sb + FKOFF + ((kb + 1) & 1) * 17408;
            uint32_t VB = sb + FVOFF + ((kb + 1) & 1) * 36864;
#pragma unroll
            for (int t = 0; t < 4; t++) {
                int idx = tid + t * 256;
                int row = idx >> 4, u = idx & 15;
                CP_ASYNC16(KB + row * 272 + u * 16, khp + (k0n + row) * 256 + u * 16);
                int vr = idx >> 3, vu = idx & 7;
                CP_ASYNC16(VB + vr * 144 + vu * 16,         vhp + (size_t)vr * (S_LEN * 2) + k0n * 2 + vu * 16);
                CP_ASYNC16(VB + 18432 + vr * 144 + vu * 16, vlp + (size_t)vr * (S_LEN * 2) + k0n * 2 + vu * 16);
            }
            CP_COMMIT();
            CP_WAIT1();
        } else {
            CP_WAIT0();
        }
        __syncthreads();

        const int k0 = kb * 64;
        // warp-skip: block fully masked for this warp's rows?
        if (k0 <= q0 + wm * 16 + 15) {
            const uint32_t KB = sb + FKOFF + (kb & 1) * 17408;
            const uint32_t VB = sb + FVOFF + (kb & 1) * 36864;

            // ---- S = Q K^T (single-pass bf16) ----
            float s[8][4];
#pragma unroll
            for (int nf = 0; nf < 8; nf++) s[nf][0] = s[nf][1] = s[nf][2] = s[nf][3] = 0.f;
#pragma unroll
            for (int ks = 0; ks < 8; ks++) {
                uint32_t aqh[4], bkh[4][4];
                uint32_t qo = (uint32_t)((wm * 16 + r16) * 272 + ks * 32 + khB);
                LDSM4(aqh, sb + FQOFF + qo);
#pragma unroll
                for (int np = 0; np < 4; np++) {
                    uint32_t ko = (uint32_t)((np * 16 + r16) * 272 + ks * 32 + khB);
                    LDSM4(bkh[np], KB + ko);
                }
#pragma unroll
                for (int nf = 0; nf < 8; nf++) {
                    const int np = nf >> 1, hs = nf & 1;
                    MMA16816(s[nf], aqh, bkh[np][hs], bkh[np][2 + hs]);
                }
            }

            if (kb >= 2 * qb) {  // blocks overlapping the diagonal
#pragma unroll
                for (int nf = 0; nf < 8; nf++)
#pragma unroll
                    for (int j = 0; j < 4; j++) {
                        int r = q0 + wm * 16 + g + ((j >> 1) << 3);
                        int c = k0 + nf * 8 + tig * 2 + (j & 1);
                        if (c > r) s[nf][j] = -1e30f;
                    }
            }

            // ---- warp-local online softmax (quad shuffles only) ----
            float rmx0 = -1e30f, rmx1 = -1e30f;
#pragma unroll
            for (int nf = 0; nf < 8; nf++) {
                rmx0 = fmaxf(rmx0, fmaxf(s[nf][0], s[nf][1]));
                rmx1 = fmaxf(rmx1, fmaxf(s[nf][2], s[nf][3]));
            }
            rmx0 = fmaxf(rmx0, __shfl_xor_sync(0xffffffffu, rmx0, 1));
            rmx0 = fmaxf(rmx0, __shfl_xor_sync(0xffffffffu, rmx0, 2));
            rmx1 = fmaxf(rmx1, __shfl_xor_sync(0xffffffffu, rmx1, 1));
            rmx1 = fmaxf(rmx1, __shfl_xor_sync(0xffffffffu, rmx1, 2));
            float mn0 = fmaxf(m_run[0], rmx0);
            float mn1 = fmaxf(m_run[1], rmx1);
            float fs0 = __expf(m_run[0] - mn0);
            float fs1 = __expf(m_run[1] - mn1);
            m_run[0] = mn0; m_run[1] = mn1;

            float sum0 = 0.f, sum1 = 0.f;
#pragma unroll
            for (int nf = 0; nf < 8; nf++) {
                s[nf][0] = __expf(s[nf][0] - mn0);
                s[nf][1] = __expf(s[nf][1] - mn0);
                s[nf][2] = __expf(s[nf][2] - mn1);
                s[nf][3] = __expf(s[nf][3] - mn1);
                sum0 += s[nf][0] + s[nf][1];
                sum1 += s[nf][2] + s[nf][3];
            }
            sum0 += __shfl_xor_sync(0xffffffffu, sum0, 1);
            sum0 += __shfl_xor_sync(0xffffffffu, sum0, 2);
            sum1 += __shfl_xor_sync(0xffffffffu, sum1, 1);
            sum1 += __shfl_xor_sync(0xffffffffu, sum1, 2);
            l_run[0] = l_run[0] * fs0 + sum0;
            l_run[1] = l_run[1] * fs1 + sum1;

#pragma unroll
            for (int i = 0; i < 16; i++) {
                o[i][0] *= fs0; o[i][1] *= fs0; o[i][2] *= fs1; o[i][3] *= fs1;
            }

            // ---- P A-frags (register reuse, split hi/lo): 4 k-steps of 16 kv ----
            uint32_t aph[4][4], apl[4][4];
#pragma unroll
            for (int kk = 0; kk < 4; kk++) {
                const int nfA = 2 * kk, nfB = 2 * kk + 1;
                split2(s[nfA][0], s[nfA][1], aph[kk][0], apl[kk][0]);
                split2(s[nfA][2], s[nfA][3], aph[kk][1], apl[kk][1]);
                split2(s[nfB][0], s[nfB][1], aph[kk][2], apl[kk][2]);
                split2(s[nfB][2], s[nfB][3], aph[kk][3], apl[kk][3]);
            }

            // ---- O += P V (split 3-pass) over full 64 kv ----
#pragma unroll
            for (int kk = 0; kk < 4; kk++) {
#pragma unroll
                for (int np = 0; np < 8; np++) {
                    uint32_t bvh[4], bvl[4];
                    uint32_t vo = (uint32_t)((np * 16 + r16) * 144 + kk * 32 + khB);
                    LDSM4(bvh, VB + vo);
                    LDSM4(bvl, VB + 18432 + vo);
#pragma unroll
                    for (int hs = 0; hs < 2; hs++) {
                        const int nd = np * 2 + hs;
                        MMA16816(o[nd], aph[kk], bvh[hs], bvh[2 + hs]);
                        MMA16816(o[nd], aph[kk], bvl[hs], bvl[2 + hs]);
                        MMA16816(o[nd], apl[kk], bvh[hs], bvh[2 + hs]);
                    }
                }
            }
        }
        __syncthreads();   // protect smem buffers before next fill
    }

    // ---- epilogue: normalize, store directly ----
    float inv0 = 1.f / l_run[0], inv1 = 1.f / l_run[1];
    float* d0 = g_ao + (size_t)(q0 + wm * 16 + g) * EMB + h * HDv;
    float* d1 = g_ao + (size_t)(q0 + wm * 16 + g + 8) * EMB + h * HDv;
#pragma unroll
    for (int nd = 0; nd < 16; nd++) {
        int c = nd * 8 + tig * 2;
        *(float2*)(d0 + c) = make_float2(o[nd][0] * inv0, o[nd][1] * inv0);
        *(float2*)(d1 + c) = make_float2(o[nd][2] * inv1, o[nd][3] * inv1);
    }
}

// ------------------- launch -------------------
extern "C" void kernel_launch(void* const* d_in, const int* in_sizes, int n_in,
                              void* d_out, int out_size)
{
    const float* hs = (const float*)d_in[0];
    const float* Wq = (const float*)d_in[1];
    const float* Wk = (const float*)d_in[2];
    const float* Wv = (const float*)d_in[3];
    const float* Wo = (const float*)d_in[4];
    const int*   pos = (const int*)d_in[6];
    float* out = (float*)d_out;

    float *p_q, *p_k, *p_v, *p_ao;
    cudaGetSymbolAddress((void**)&p_q,  g_q);
    cudaGetSymbolAddress((void**)&p_k,  g_k);
    cudaGetSymbolAddress((void**)&p_v,  g_v);
    cudaGetSymbolAddress((void**)&p_ao, g_ao);
    __nv_bfloat16 *p_ah, *p_al, *p_aoh, *p_aol;
    __nv_bfloat16 *p_wqh, *p_wql, *p_wkh, *p_wkl, *p_wvh, *p_wvl, *p_woh, *p_wol;
    __nv_bfloat16 *p_qh, *p_kh, *p_vth, *p_vtl;
    cudaGetSymbolAddress((void**)&p_ah,  g_ah);
    cudaGetSymbolAddress((void**)&p_al,  g_al);
    cudaGetSymbolAddress((void**)&p_aoh, g_aoh);
    cudaGetSymbolAddress((void**)&p_aol, g_aol);
    cudaGetSymbolAddress((void**)&p_wqh, g_wqh);
    cudaGetSymbolAddress((void**)&p_wql, g_wql);
    cudaGetSymbolAddress((void**)&p_wkh, g_wkh);
    cudaGetSymbolAddress((void**)&p_wkl, g_wkl);
    cudaGetSymbolAddress((void**)&p_wvh, g_wvh);
    cudaGetSymbolAddress((void**)&p_wvl, g_wvl);
    cudaGetSymbolAddress((void**)&p_woh, g_woh);
    cudaGetSymbolAddress((void**)&p_wol, g_wol);
    cudaGetSymbolAddress((void**)&p_qh,  g_qh);
    cudaGetSymbolAddress((void**)&p_kh,  g_kh);
    cudaGetSymbolAddress((void**)&p_vth, g_vth);
    cudaGetSymbolAddress((void**)&p_vtl, g_vtl);

    cudaFuncSetAttribute(tgemm_kernel, cudaFuncAttributeMaxDynamicSharedMemorySize, TG_SMEM);
    cudaFuncSetAttribute(flash_mma_kernel, cudaFuncAttributeMaxDynamicSharedMemorySize, FA2_SMEM);

    // 0) split conversions
    conv_split_kernel<<<(S_LEN * EMB / 4 + 255) / 256, 256>>>(hs, p_ah, p_al, S_LEN * EMB / 4);
    conv_split_t_kernel<<<dim3(EMB / 32, EMB / 32), dim3(32, 8)>>>(Wq, p_wqh, p_wql, EMB, EMB);
    conv_split_t_kernel<<<dim3(KVD / 32, EMB / 32), dim3(32, 8)>>>(Wk, p_wkh, p_wkl, EMB, KVD);
    conv_split_t_kernel<<<dim3(KVD / 32, EMB / 32), dim3(32, 8)>>>(Wv, p_wvh, p_wvl, EMB, KVD);
    conv_split_t_kernel<<<dim3(EMB / 32, EMB / 32), dim3(32, 8)>>>(Wo, p_woh, p_wol, EMB, EMB);

    // 1) projections (HMMA)
    tgemm_kernel<<<dim3(EMB / 128, S_LEN / 128), 256, TG_SMEM>>>(p_ah, p_al, p_wqh, p_wql, p_q, EMB, EMB);
    tgemm_kernel<<<dim3(KVD / 128, S_LEN / 128), 256, TG_SMEM>>>(p_ah, p_al, p_wkh, p_wkl, p_k, KVD, EMB);
    tgemm_kernel<<<dim3(KVD / 128, S_LEN / 128), 256, TG_SMEM>>>(p_ah, p_al, p_wvh, p_wvl, p_v, KVD, EMB);

    // 2) RoPE -> bf16 attention operands (Q/K hi-only; V split)
    rope_table_kernel<<<S_LEN, 64>>>(pos);
    rope_bf16_kernel<<<dim3(S_LEN, NHEADS), 64>>>(p_q, p_qh, EMB, 0.08838834764831845f);
    rope_bf16_kernel<<<dim3(S_LEN, NKVH),  64>>>(p_k, p_kh, KVD, 1.0f);
    conv_split_t_kernel<<<dim3(KVD / 32, S_LEN / 32), dim3(32, 8)>>>(p_v, p_vth, p_vtl, S_LEN, KVD);

    // 3) causal flash attention (HMMA, BM=128, bf16 QK^T)
    flash_mma_kernel<<<dim3(S_LEN / 128, NHEADS), 256, FA2_SMEM>>>();

    // 4) output projection (HMMA)
    conv_split_kernel<<<(S_LEN * EMB / 4 + 255) / 256, 256>>>(p_ao, p_aoh, p_aol, S_LEN * EMB / 4);
    tgemm_kernel<<<dim3(EMB / 128, S_LEN / 128), 256, TG_SMEM>>>(p_aoh, p_aol, p_woh, p_wol, out, EMB, EMB);
}